// round 1
// baseline (speedup 1.0000x reference)
#include <cuda_runtime.h>

#define N_MAX 50000
#define E_MAX 1600000
#define ET_MAX (N_MAX + E_MAX)
#define FIN 128
#define F1 256
#define HID 64

#define NEG_SLOPE 0.2f
#define LN_EPS 1e-5f

// ------------------------- scratch (device globals; no allocation) ----------
__device__ float g_xn[(size_t)N_MAX * FIN];     // normalized node features
__device__ float g_xw1[(size_t)N_MAX * F1];     // layer-1 projected features
__device__ float g_as1[N_MAX * 4];
__device__ float g_ad1[N_MAX * 4];
__device__ float g_h2[(size_t)N_MAX * F1];      // layer-1 output (ELU)
__device__ float g_xw2[(size_t)N_MAX * HID];    // layer-2 projected
__device__ float g_as2[N_MAX];
__device__ float g_ad2[N_MAX];
__device__ float g_h3[(size_t)N_MAX * HID];     // layer-2 output (ELU)
__device__ int   g_off[N_MAX + 1];              // CSR offsets (by dst)
__device__ int   g_cur[N_MAX];                  // degree counts / cursors
__device__ int   g_csrc[ET_MAX];                // CSR src node ids
__device__ float g_cvec[F1];                    // regime contribution bias
__device__ unsigned g_maxbits;                  // encoded global max (softmax)
__device__ float g_sumexp;

static __device__ __forceinline__ float lrelu(float x) { return x > 0.f ? x : NEG_SLOPE * x; }
static __device__ __forceinline__ float eluf(float x)  { return x > 0.f ? x : (__expf(x) - 1.f); }
static __device__ __forceinline__ float dec_max(unsigned u) {
    return (u & 0x80000000u) ? __uint_as_float(u & 0x7fffffffu) : __uint_as_float(~u);
}

// ------------------------- init -------------------------
__global__ void k_init(int n) {
    int i = blockIdx.x * blockDim.x + threadIdx.x;
    if (i < n) g_cur[i] = 0;
    if (i == 0) { g_maxbits = 0u; g_sumexp = 0.f; }
}

// ------------------------- row layernorm (warp per row) -------------------------
__global__ void __launch_bounds__(256) k_rownorm(
    const float* __restrict__ x, const float* __restrict__ gamma,
    const float* __restrict__ beta, int n)
{
    int w = (blockIdx.x * blockDim.x + threadIdx.x) >> 5;
    int l = threadIdx.x & 31;
    if (w >= n) return;
    float4 v = ((const float4*)(x + (size_t)w * FIN))[l];
    float s  = v.x + v.y + v.z + v.w;
    float ss = v.x*v.x + v.y*v.y + v.z*v.z + v.w*v.w;
#pragma unroll
    for (int off = 16; off; off >>= 1) {
        s  += __shfl_xor_sync(0xffffffffu, s, off);
        ss += __shfl_xor_sync(0xffffffffu, ss, off);
    }
    float mu = s * (1.f / FIN);
    float var = ss * (1.f / FIN) - mu * mu;
    float rstd = rsqrtf(var + LN_EPS);
    float4 g = ((const float4*)gamma)[l];
    float4 b = ((const float4*)beta)[l];
    float4 o;
    o.x = (v.x - mu) * rstd * g.x + b.x;
    o.y = (v.y - mu) * rstd * g.y + b.y;
    o.z = (v.z - mu) * rstd * g.z + b.z;
    o.w = (v.w - mu) * rstd * g.w + b.w;
    ((float4*)(g_xn + (size_t)w * FIN))[l] = o;
}

// ------------------------- regime LN + fold into per-column bias ----------------
__global__ void k_cvec(const float* __restrict__ reg, const float* __restrict__ rg,
                       const float* __restrict__ rb, const float* __restrict__ W1)
{
    __shared__ float rn[16];
    int t = threadIdx.x;
    if (t == 0) {
        float s = 0.f;
        for (int k = 0; k < 16; k++) s += reg[k];
        float mu = s * (1.f / 16.f);
        float ss = 0.f;
        for (int k = 0; k < 16; k++) { float d = reg[k] - mu; ss += d * d; }
        float rstd = rsqrtf(ss * (1.f / 16.f) + LN_EPS);
        for (int k = 0; k < 16; k++) rn[k] = (reg[k] - mu) * rstd * rg[k] + rb[k];
    }
    __syncthreads();
    if (t < F1) {
        float s = 0.f;
#pragma unroll
        for (int k = 0; k < 16; k++) s += rn[k] * W1[(size_t)(FIN + k) * F1 + t];
        g_cvec[t] = s;
    }
}

// ------------------------- SGEMM (SEL=0: xn@W1part -> xw1 + cvec; SEL=1: h2@W2 -> xw2)
template <int SEL, int BM, int BN, int BK, int TM, int TN>
__global__ void __launch_bounds__(256) k_sgemm(const float* __restrict__ B,
                                               int M, int Nn, int K)
{
    const float* A = (SEL == 0) ? g_xn : g_h2;
    float*       C = (SEL == 0) ? g_xw1 : g_xw2;

    constexpr int TX = BN / TN;  // 16
    constexpr int TY = BM / TM;  // 16
    __shared__ __align__(16) float As[BK][BM + 4];
    __shared__ __align__(16) float Bs[BK][BN];

    int tid = threadIdx.x;
    int tx = tid % TX, ty = tid / TX;
    int rb = blockIdx.y * BM;
    int cb = blockIdx.x * BN;

    float acc[TM][TN];
#pragma unroll
    for (int i = 0; i < TM; i++)
#pragma unroll
        for (int j = 0; j < TN; j++) acc[i][j] = 0.f;

    constexpr int ASLOTS = BM * BK / 4;
    constexpr int BSLOTS = BK * BN / 4;
    constexpr int NT = TX * TY;

    for (int k0 = 0; k0 < K; k0 += BK) {
#pragma unroll
        for (int s = tid; s < ASLOTS; s += NT) {
            int r  = s / (BK / 4);
            int kk = (s % (BK / 4)) * 4;
            float4 v = make_float4(0.f, 0.f, 0.f, 0.f);
            int gr = rb + r;
            if (gr < M) v = *(const float4*)(A + (size_t)gr * K + k0 + kk);
            As[kk + 0][r] = v.x; As[kk + 1][r] = v.y;
            As[kk + 2][r] = v.z; As[kk + 3][r] = v.w;
        }
#pragma unroll
        for (int s = tid; s < BSLOTS; s += NT) {
            int r  = s / (BN / 4);
            int cc = (s % (BN / 4)) * 4;
            *(float4*)&Bs[r][cc] = *(const float4*)(B + (size_t)(k0 + r) * Nn + cb + cc);
        }
        __syncthreads();
#pragma unroll
        for (int k = 0; k < BK; k++) {
            const float4* Ap = (const float4*)&As[k][ty * TM];
            const float4* Bp = (const float4*)&Bs[k][tx * TN];
            float4 a0 = Ap[0], a1 = Ap[1];
            float4 b0 = Bp[0];
            float av[TM] = {a0.x, a0.y, a0.z, a0.w, a1.x, a1.y, a1.z, a1.w};
            float bv[TN] = {b0.x, b0.y, b0.z, b0.w};
#pragma unroll
            for (int i = 0; i < TM; i++)
#pragma unroll
                for (int j = 0; j < TN; j++) acc[i][j] += av[i] * bv[j];
        }
        __syncthreads();
    }

#pragma unroll
    for (int i = 0; i < TM; i++) {
        int gr = rb + ty * TM + i;
        if (gr >= M) continue;
        int col = cb + tx * TN;
        float4 o;
        if (SEL == 0) {
            o.x = acc[i][0] + g_cvec[col + 0];
            o.y = acc[i][1] + g_cvec[col + 1];
            o.z = acc[i][2] + g_cvec[col + 2];
            o.w = acc[i][3] + g_cvec[col + 3];
        } else {
            o.x = acc[i][0]; o.y = acc[i][1]; o.z = acc[i][2]; o.w = acc[i][3];
        }
        *(float4*)(C + (size_t)gr * Nn + col) = o;
    }
}

// ------------------------- alpha dots, layer 1 (warp per row) -------------------
__global__ void __launch_bounds__(256) k_alpha1(const float* __restrict__ asrc,
                                                const float* __restrict__ adst, int n)
{
    int w = (blockIdx.x * blockDim.x + threadIdx.x) >> 5;
    int l = threadIdx.x & 31;
    if (w >= n) return;
    const float4* xr = (const float4*)(g_xw1 + (size_t)w * F1);
    float4 x1 = xr[l], x2 = xr[32 + l];
    float4 s1 = ((const float4*)asrc)[l], s2 = ((const float4*)asrc)[32 + l];
    float4 d1 = ((const float4*)adst)[l], d2 = ((const float4*)adst)[32 + l];
    float ps1 = x1.x*s1.x + x1.y*s1.y + x1.z*s1.z + x1.w*s1.w;
    float ps2 = x2.x*s2.x + x2.y*s2.y + x2.z*s2.z + x2.w*s2.w;
    float pd1 = x1.x*d1.x + x1.y*d1.y + x1.z*d1.z + x1.w*d1.w;
    float pd2 = x2.x*d2.x + x2.y*d2.y + x2.z*d2.z + x2.w*d2.w;
#pragma unroll
    for (int off = 8; off; off >>= 1) {
        ps1 += __shfl_xor_sync(0xffffffffu, ps1, off);
        ps2 += __shfl_xor_sync(0xffffffffu, ps2, off);
        pd1 += __shfl_xor_sync(0xffffffffu, pd1, off);
        pd2 += __shfl_xor_sync(0xffffffffu, pd2, off);
    }
    if (l == 0)  { g_as1[w*4+0] = ps1; g_as1[w*4+2] = ps2; g_ad1[w*4+0] = pd1; g_ad1[w*4+2] = pd2; }
    if (l == 16) { g_as1[w*4+1] = ps1; g_as1[w*4+3] = ps2; g_ad1[w*4+1] = pd1; g_ad1[w*4+3] = pd2; }
}

// ------------------------- alpha dots, layer 2 (warp per row) -------------------
__global__ void __launch_bounds__(256) k_alpha2(const float* __restrict__ asrc,
                                                const float* __restrict__ adst, int n)
{
    int w = (blockIdx.x * blockDim.x + threadIdx.x) >> 5;
    int l = threadIdx.x & 31;
    if (w >= n) return;
    float x0 = g_xw2[(size_t)w * HID + l];
    float x1 = g_xw2[(size_t)w * HID + 32 + l];
    float p = x0 * asrc[l] + x1 * asrc[32 + l];
    float q = x0 * adst[l] + x1 * adst[32 + l];
#pragma unroll
    for (int off = 16; off; off >>= 1) {
        p += __shfl_xor_sync(0xffffffffu, p, off);
        q += __shfl_xor_sync(0xffffffffu, q, off);
    }
    if (l == 0) { g_as2[w] = p; g_ad2[w] = q; }
}

// ------------------------- CSR build -------------------------
__global__ void k_count(const int* __restrict__ ei, int e, int etot) {
    int i = blockIdx.x * blockDim.x + threadIdx.x;
    if (i >= etot) return;
    int d = (i < e) ? ei[e + i] : (i - e);
    atomicAdd(&g_cur[d], 1);
}

__global__ void k_scan(int n) {
    __shared__ int sh[1024];
    __shared__ int running;
    int tid = threadIdx.x;
    if (tid == 0) running = 0;
    __syncthreads();
    for (int base = 0; base < n; base += 1024) {
        int i = base + tid;
        int v = (i < n) ? g_cur[i] : 0;
        sh[tid] = v;
        __syncthreads();
        for (int off = 1; off < 1024; off <<= 1) {
            int t = (tid >= off) ? sh[tid - off] : 0;
            __syncthreads();
            sh[tid] += t;
            __syncthreads();
        }
        int excl = running + sh[tid] - v;
        if (i < n) { g_off[i] = excl; g_cur[i] = excl; }
        __syncthreads();
        if (tid == 0) running += sh[1023];
        __syncthreads();
    }
    if (tid == 0) g_off[n] = running;
}

__global__ void k_scatter(const int* __restrict__ ei, int e, int etot) {
    int i = blockIdx.x * blockDim.x + threadIdx.x;
    if (i >= etot) return;
    int s, d;
    if (i < e) { s = ei[i]; d = ei[e + i]; } else { s = d = i - e; }
    int pos = atomicAdd(&g_cur[d], 1);
    g_csrc[pos] = s;
}

// ------------------------- GAT layer-1 aggregation (warp per dst node) ----------
__global__ void __launch_bounds__(256) k_agg1(const float* __restrict__ b1, int n) {
    int w = (blockIdx.x * blockDim.x + threadIdx.x) >> 5;
    int l = threadIdx.x & 31;
    if (w >= n) return;
    int start = g_off[w], end = g_off[w + 1];
    float4 adv = ((const float4*)g_ad1)[w];
    float ad0 = adv.x, ad1 = adv.y, ad2 = adv.z, ad3 = adv.w;

    float m0 = -3.402823466e38f, m1 = m0, m2 = m0, m3 = m0;
    for (int i = start + l; i < end; i += 32) {
        int s = g_csrc[i];
        float4 t = ((const float4*)g_as1)[s];
        m0 = fmaxf(m0, lrelu(t.x + ad0));
        m1 = fmaxf(m1, lrelu(t.y + ad1));
        m2 = fmaxf(m2, lrelu(t.z + ad2));
        m3 = fmaxf(m3, lrelu(t.w + ad3));
    }
#pragma unroll
    for (int off = 16; off; off >>= 1) {
        m0 = fmaxf(m0, __shfl_xor_sync(0xffffffffu, m0, off));
        m1 = fmaxf(m1, __shfl_xor_sync(0xffffffffu, m1, off));
        m2 = fmaxf(m2, __shfl_xor_sync(0xffffffffu, m2, off));
        m3 = fmaxf(m3, __shfl_xor_sync(0xffffffffu, m3, off));
    }

    float4 acc1 = make_float4(0.f, 0.f, 0.f, 0.f);
    float4 acc2 = make_float4(0.f, 0.f, 0.f, 0.f);
    float d0 = 0.f, d1 = 0.f, d2 = 0.f, d3 = 0.f;
    const float4* asv = (const float4*)g_as1;
    bool lo = (l < 16);
    int i = start;
    for (; i + 2 <= end; i += 2) {
        int s0 = g_csrc[i], s1 = g_csrc[i + 1];
        float4 t0 = asv[s0], t1 = asv[s1];
        const float4* x0p = (const float4*)(g_xw1 + (size_t)s0 * F1);
        const float4* x1p = (const float4*)(g_xw1 + (size_t)s1 * F1);
        float4 xa0 = x0p[l], xb0 = x0p[32 + l];
        float4 xa1 = x1p[l], xb1 = x1p[32 + l];
        float w00 = __expf(lrelu(t0.x + ad0) - m0), w01 = __expf(lrelu(t0.y + ad1) - m1);
        float w02 = __expf(lrelu(t0.z + ad2) - m2), w03 = __expf(lrelu(t0.w + ad3) - m3);
        float w10 = __expf(lrelu(t1.x + ad0) - m0), w11 = __expf(lrelu(t1.y + ad1) - m1);
        float w12 = __expf(lrelu(t1.z + ad2) - m2), w13 = __expf(lrelu(t1.w + ad3) - m3);
        d0 += w00 + w10; d1 += w01 + w11; d2 += w02 + w12; d3 += w03 + w13;
        float wa0 = lo ? w00 : w01, wb0 = lo ? w02 : w03;
        float wa1 = lo ? w10 : w11, wb1 = lo ? w12 : w13;
        acc1.x += xa0.x * wa0 + xa1.x * wa1;
        acc1.y += xa0.y * wa0 + xa1.y * wa1;
        acc1.z += xa0.z * wa0 + xa1.z * wa1;
        acc1.w += xa0.w * wa0 + xa1.w * wa1;
        acc2.x += xb0.x * wb0 + xb1.x * wb1;
        acc2.y += xb0.y * wb0 + xb1.y * wb1;
        acc2.z += xb0.z * wb0 + xb1.z * wb1;
        acc2.w += xb0.w * wb0 + xb1.w * wb1;
    }
    if (i < end) {
        int s0 = g_csrc[i];
        float4 t0 = asv[s0];
        const float4* x0p = (const float4*)(g_xw1 + (size_t)s0 * F1);
        float4 xa0 = x0p[l], xb0 = x0p[32 + l];
        float w00 = __expf(lrelu(t0.x + ad0) - m0), w01 = __expf(lrelu(t0.y + ad1) - m1);
        float w02 = __expf(lrelu(t0.z + ad2) - m2), w03 = __expf(lrelu(t0.w + ad3) - m3);
        d0 += w00; d1 += w01; d2 += w02; d3 += w03;
        float wa0 = lo ? w00 : w01, wb0 = lo ? w02 : w03;
        acc1.x += xa0.x * wa0; acc1.y += xa0.y * wa0;
        acc1.z += xa0.z * wa0; acc1.w += xa0.w * wa0;
        acc2.x += xb0.x * wb0; acc2.y += xb0.y * wb0;
        acc2.z += xb0.z * wb0; acc2.w += xb0.w * wb0;
    }
    float rda = 1.f / (lo ? d0 : d1);
    float rdb = 1.f / (lo ? d2 : d3);
    float4 bb1 = ((const float4*)b1)[l], bb2 = ((const float4*)b1)[32 + l];
    float4 o1, o2;
    o1.x = eluf(acc1.x * rda + bb1.x); o1.y = eluf(acc1.y * rda + bb1.y);
    o1.z = eluf(acc1.z * rda + bb1.z); o1.w = eluf(acc1.w * rda + bb1.w);
    o2.x = eluf(acc2.x * rdb + bb2.x); o2.y = eluf(acc2.y * rdb + bb2.y);
    o2.z = eluf(acc2.z * rdb + bb2.z); o2.w = eluf(acc2.w * rdb + bb2.w);
    float* outp = g_h2 + (size_t)w * F1;
    ((float4*)outp)[l] = o1;
    ((float4*)outp)[32 + l] = o2;
}

// ------------------------- GAT layer-2 aggregation (warp per dst node) ----------
__global__ void __launch_bounds__(256) k_agg2(const float* __restrict__ b2, int n) {
    int w = (blockIdx.x * blockDim.x + threadIdx.x) >> 5;
    int l = threadIdx.x & 31;
    if (w >= n) return;
    int start = g_off[w], end = g_off[w + 1];
    float adv = g_ad2[w];
    float m = -3.402823466e38f;
    for (int i = start + l; i < end; i += 32)
        m = fmaxf(m, lrelu(g_as2[g_csrc[i]] + adv));
#pragma unroll
    for (int off = 16; off; off >>= 1)
        m = fmaxf(m, __shfl_xor_sync(0xffffffffu, m, off));

    float2 acc = make_float2(0.f, 0.f);
    float den = 0.f;
    int i = start;
    for (; i + 2 <= end; i += 2) {
        int s0 = g_csrc[i], s1 = g_csrc[i + 1];
        float e0 = __expf(lrelu(g_as2[s0] + adv) - m);
        float e1 = __expf(lrelu(g_as2[s1] + adv) - m);
        float2 x0 = ((const float2*)(g_xw2 + (size_t)s0 * HID))[l];
        float2 x1 = ((const float2*)(g_xw2 + (size_t)s1 * HID))[l];
        den += e0 + e1;
        acc.x += x0.x * e0 + x1.x * e1;
        acc.y += x0.y * e0 + x1.y * e1;
    }
    if (i < end) {
        int s0 = g_csrc[i];
        float e0 = __expf(lrelu(g_as2[s0] + adv) - m);
        float2 x0 = ((const float2*)(g_xw2 + (size_t)s0 * HID))[l];
        den += e0;
        acc.x += x0.x * e0;
        acc.y += x0.y * e0;
    }
    float r = 1.f / den;
    float2 bb = ((const float2*)b2)[l];
    float2 o;
    o.x = eluf(acc.x * r + bb.x);
    o.y = eluf(acc.y * r + bb.y);
    ((float2*)(g_h3 + (size_t)w * HID))[l] = o;
}

// ------------------------- logits + block max (warp per row) --------------------
__global__ void __launch_bounds__(256) k_logits(const float* __restrict__ Wout,
                                                const float* __restrict__ bout,
                                                float* __restrict__ out, int n)
{
    __shared__ float sm[8];
    int wi = threadIdx.x >> 5;
    int l = threadIdx.x & 31;
    int row = blockIdx.x * 8 + wi;
    float lg = -3.402823466e38f;
    if (row < n) {
        float2 hv = ((const float2*)(g_h3 + (size_t)row * HID))[l];
        float2 wv = ((const float2*)Wout)[l];
        float p = hv.x * wv.x + hv.y * wv.y;
#pragma unroll
        for (int off = 16; off; off >>= 1) p += __shfl_xor_sync(0xffffffffu, p, off);
        lg = p + bout[0];
        if (l == 0) out[n + row] = lg;
    }
    if (l == 0) sm[wi] = lg;
    __syncthreads();
    if (threadIdx.x == 0) {
        float mx = sm[0];
#pragma unroll
        for (int k = 1; k < 8; k++) mx = fmaxf(mx, sm[k]);
        unsigned u = __float_as_uint(mx);
        u = (u & 0x80000000u) ? ~u : (u | 0x80000000u);
        atomicMax(&g_maxbits, u);
    }
}

__global__ void k_expsum(const float* __restrict__ out, int n) {
    __shared__ float sm[256];
    float M = dec_max(g_maxbits);
    float s = 0.f;
    for (int i = blockIdx.x * blockDim.x + threadIdx.x; i < n; i += gridDim.x * blockDim.x)
        s += __expf(out[n + i] - M);
    sm[threadIdx.x] = s;
    __syncthreads();
    for (int off = 128; off; off >>= 1) {
        if (threadIdx.x < off) sm[threadIdx.x] += sm[threadIdx.x + off];
        __syncthreads();
    }
    if (threadIdx.x == 0) atomicAdd(&g_sumexp, sm[0]);
}

__global__ void k_weights(float* __restrict__ out, int n) {
    int i = blockIdx.x * blockDim.x + threadIdx.x;
    if (i >= n) return;
    float M = dec_max(g_maxbits);
    float S = g_sumexp;
    out[i] = __expf(out[n + i] - M) / S;
}

// ------------------------- launch -------------------------
extern "C" void kernel_launch(void* const* d_in, const int* in_sizes, int n_in,
                              void* d_out, int out_size)
{
    const float* x    = (const float*)d_in[0];
    const int*   ei   = (const int*)d_in[1];
    const float* reg  = (const float*)d_in[2];
    const float* ng   = (const float*)d_in[3];
    const float* nb   = (const float*)d_in[4];
    const float* rg   = (const float*)d_in[5];
    const float* rb   = (const float*)d_in[6];
    const float* W1   = (const float*)d_in[7];
    const float* as1  = (const float*)d_in[8];
    const float* ad1  = (const float*)d_in[9];
    const float* b1   = (const float*)d_in[10];
    const float* W2   = (const float*)d_in[11];
    const float* as2  = (const float*)d_in[12];
    const float* ad2  = (const float*)d_in[13];
    const float* b2   = (const float*)d_in[14];
    const float* Wout = (const float*)d_in[15];
    const float* bout = (const float*)d_in[16];
    float* out = (float*)d_out;

    int n = in_sizes[0] / FIN;
    int e = in_sizes[1] / 2;
    int etot = e + n;
    int wb = (n + 7) / 8;  // warp-per-row grids (8 warps / 256-thread block)

    k_init<<<(n + 255) / 256, 256>>>(n);
    k_rownorm<<<wb, 256>>>(x, ng, nb, n);
    k_cvec<<<1, 256>>>(reg, rg, rb, W1);

    // GEMM1: xw1[n,256] = xn[n,128] @ W1[0:128,:] + cvec
    dim3 g1(F1 / 64, (n + 127) / 128);
    k_sgemm<0, 128, 64, 16, 8, 4><<<g1, 256>>>(W1, n, F1, FIN);

    k_alpha1<<<wb, 256>>>(as1, ad1, n);

    // CSR build (by destination)
    k_count<<<(etot + 255) / 256, 256>>>(ei, e, etot);
    k_scan<<<1, 1024>>>(n);
    k_scatter<<<(etot + 255) / 256, 256>>>(ei, e, etot);

    k_agg1<<<wb, 256>>>(b1, n);

    // GEMM2: xw2[n,64] = h2[n,256] @ W2[256,64]
    dim3 g2(1, (n + 127) / 128);
    k_sgemm<1, 128, 64, 16, 8, 4><<<g2, 256>>>(W2, n, HID, F1);

    k_alpha2<<<wb, 256>>>(as2, ad2, n);
    k_agg2<<<wb, 256>>>(b2, n);

    k_logits<<<wb, 256>>>(Wout, bout, out, n);
    k_expsum<<<256, 256>>>(out, n);
    k_weights<<<(n + 255) / 256, 256>>>(out, n);
}

// round 2
// speedup vs baseline: 1.1655x; 1.1655x over previous
#include <cuda_runtime.h>
#include <cuda_fp16.h>

#define N_MAX 50000
#define E_MAX 1600000
#define ET_MAX (N_MAX + E_MAX)
#define FIN 128
#define F1 256
#define HID 64

#define NEG_SLOPE 0.2f
#define LN_EPS 1e-5f

// ------------------------- scratch (device globals; no allocation) ----------
__device__ float  g_xn[(size_t)N_MAX * FIN];     // normalized node features
__device__ __half g_xw1h[(size_t)N_MAX * F1];    // layer-1 projected (fp16 for gathers)
__device__ float  g_as1[N_MAX * 4];
__device__ float  g_ad1[N_MAX * 4];
__device__ float  g_h2[(size_t)N_MAX * F1];      // layer-1 output (ELU, fp32)
__device__ float  g_xw2[(size_t)N_MAX * HID];    // layer-2 projected (fp32)
__device__ float  g_as2[N_MAX];
__device__ float  g_ad2[N_MAX];
__device__ float  g_h3[(size_t)N_MAX * HID];     // layer-2 output (ELU)
__device__ int    g_off[N_MAX + 1];              // CSR offsets (by dst)
__device__ int    g_cur[N_MAX];                  // degree counts / cursors
__device__ int    g_csrc[ET_MAX];                // CSR src node ids
__device__ float  g_cvec[F1];                    // regime contribution bias
__device__ int    g_bsum[64];                    // scan block totals
__device__ int    g_bpre[64];                    // scan block prefixes
__device__ unsigned g_maxbits;                   // encoded global max (softmax)
__device__ float  g_sumexp;

static __device__ __forceinline__ float lrelu(float x) { return x > 0.f ? x : NEG_SLOPE * x; }
static __device__ __forceinline__ float eluf(float x)  { return x > 0.f ? x : (__expf(x) - 1.f); }
static __device__ __forceinline__ float dec_max(unsigned u) {
    return (u & 0x80000000u) ? __uint_as_float(u & 0x7fffffffu) : __uint_as_float(~u);
}
static __device__ __forceinline__ float4 h4f(uint2 u) {
    __half2 a = *(__half2*)&u.x;
    __half2 b = *(__half2*)&u.y;
    float2 fa = __half22float2(a), fb = __half22float2(b);
    return make_float4(fa.x, fa.y, fb.x, fb.y);
}

// ------------------------- init -------------------------
__global__ void k_init(int n) {
    int i = blockIdx.x * blockDim.x + threadIdx.x;
    if (i < n) g_cur[i] = 0;
    if (i == 0) { g_maxbits = 0u; g_sumexp = 0.f; }
}

// ------------------------- row layernorm (warp per row) -------------------------
__global__ void __launch_bounds__(256) k_rownorm(
    const float* __restrict__ x, const float* __restrict__ gamma,
    const float* __restrict__ beta, int n)
{
    int w = (blockIdx.x * blockDim.x + threadIdx.x) >> 5;
    int l = threadIdx.x & 31;
    if (w >= n) return;
    float4 v = ((const float4*)(x + (size_t)w * FIN))[l];
    float s  = v.x + v.y + v.z + v.w;
    float ss = v.x*v.x + v.y*v.y + v.z*v.z + v.w*v.w;
#pragma unroll
    for (int off = 16; off; off >>= 1) {
        s  += __shfl_xor_sync(0xffffffffu, s, off);
        ss += __shfl_xor_sync(0xffffffffu, ss, off);
    }
    float mu = s * (1.f / FIN);
    float var = ss * (1.f / FIN) - mu * mu;
    float rstd = rsqrtf(var + LN_EPS);
    float4 g = ((const float4*)gamma)[l];
    float4 b = ((const float4*)beta)[l];
    float4 o;
    o.x = (v.x - mu) * rstd * g.x + b.x;
    o.y = (v.y - mu) * rstd * g.y + b.y;
    o.z = (v.z - mu) * rstd * g.z + b.z;
    o.w = (v.w - mu) * rstd * g.w + b.w;
    ((float4*)(g_xn + (size_t)w * FIN))[l] = o;
}

// ------------------------- regime LN + fold into per-column bias ----------------
__global__ void k_cvec(const float* __restrict__ reg, const float* __restrict__ rg,
                       const float* __restrict__ rb, const float* __restrict__ W1)
{
    __shared__ float rn[16];
    int t = threadIdx.x;
    if (t == 0) {
        float s = 0.f;
        for (int k = 0; k < 16; k++) s += reg[k];
        float mu = s * (1.f / 16.f);
        float ss = 0.f;
        for (int k = 0; k < 16; k++) { float d = reg[k] - mu; ss += d * d; }
        float rstd = rsqrtf(ss * (1.f / 16.f) + LN_EPS);
        for (int k = 0; k < 16; k++) rn[k] = (reg[k] - mu) * rstd * rg[k] + rb[k];
    }
    __syncthreads();
    if (t < F1) {
        float s = 0.f;
#pragma unroll
        for (int k = 0; k < 16; k++) s += rn[k] * W1[(size_t)(FIN + k) * F1 + t];
        g_cvec[t] = s;
    }
}

// ------------------------- SGEMM: 8x8 register tile, 256 threads ----------------
// SEL=0: g_xn[n,128] @ W1[0:128,256] + cvec -> g_xw1h (half).  BM=128, BN=128.
// SEL=1: g_h2[n,256] @ W2[256,64]          -> g_xw2 (fp32).    BM=256, BN=64.
template <int SEL, int BM, int BN>
__global__ void __launch_bounds__(256) k_gemm(const float* __restrict__ Bm,
                                              int M, int Nn, int K)
{
    constexpr int BK = 16;
    constexpr int TX = BN / 8;
    __shared__ __align__(16) float As[BK][BM + 4];
    __shared__ __align__(16) float Bs[BK][BN];

    const float* A = (SEL == 0) ? g_xn : g_h2;

    int tid = threadIdx.x;
    int tx = tid % TX, ty = tid / TX;
    int rb = blockIdx.y * BM;
    int cb = blockIdx.x * BN;

    float acc[8][8];
#pragma unroll
    for (int i = 0; i < 8; i++)
#pragma unroll
        for (int j = 0; j < 8; j++) acc[i][j] = 0.f;

    constexpr int A4 = BM * BK / 4;
    constexpr int B4 = BK * BN / 4;

    for (int k0 = 0; k0 < K; k0 += BK) {
#pragma unroll
        for (int s = tid; s < A4; s += 256) {
            int r  = s / (BK / 4);
            int kk = (s % (BK / 4)) * 4;
            float4 v = make_float4(0.f, 0.f, 0.f, 0.f);
            int gr = rb + r;
            if (gr < M) v = *(const float4*)(A + (size_t)gr * K + k0 + kk);
            As[kk + 0][r] = v.x; As[kk + 1][r] = v.y;
            As[kk + 2][r] = v.z; As[kk + 3][r] = v.w;
        }
#pragma unroll
        for (int s = tid; s < B4; s += 256) {
            int r  = s / (BN / 4);
            int cc = (s % (BN / 4)) * 4;
            *(float4*)&Bs[r][cc] = *(const float4*)(Bm + (size_t)(k0 + r) * Nn + cb + cc);
        }
        __syncthreads();
#pragma unroll
        for (int k = 0; k < BK; k++) {
            float4 a0 = *(const float4*)&As[k][ty * 8];
            float4 a1 = *(const float4*)&As[k][ty * 8 + 4];
            float4 b0 = *(const float4*)&Bs[k][tx * 8];
            float4 b1 = *(const float4*)&Bs[k][tx * 8 + 4];
            float av[8] = {a0.x, a0.y, a0.z, a0.w, a1.x, a1.y, a1.z, a1.w};
            float bv[8] = {b0.x, b0.y, b0.z, b0.w, b1.x, b1.y, b1.z, b1.w};
#pragma unroll
            for (int i = 0; i < 8; i++)
#pragma unroll
                for (int j = 0; j < 8; j++) acc[i][j] += av[i] * bv[j];
        }
        __syncthreads();
    }

    int col = cb + tx * 8;
    if (SEL == 0) {
        float4 c0 = *(const float4*)(g_cvec + col);
        float4 c1 = *(const float4*)(g_cvec + col + 4);
#pragma unroll
        for (int i = 0; i < 8; i++) {
            int gr = rb + ty * 8 + i;
            if (gr >= M) continue;
            union { __half2 h2[4]; uint4 u; } cv;
            cv.h2[0] = __floats2half2_rn(acc[i][0] + c0.x, acc[i][1] + c0.y);
            cv.h2[1] = __floats2half2_rn(acc[i][2] + c0.z, acc[i][3] + c0.w);
            cv.h2[2] = __floats2half2_rn(acc[i][4] + c1.x, acc[i][5] + c1.y);
            cv.h2[3] = __floats2half2_rn(acc[i][6] + c1.z, acc[i][7] + c1.w);
            *(uint4*)(g_xw1h + (size_t)gr * F1 + col) = cv.u;
        }
    } else {
#pragma unroll
        for (int i = 0; i < 8; i++) {
            int gr = rb + ty * 8 + i;
            if (gr >= M) continue;
            float* cp = g_xw2 + (size_t)gr * Nn + col;
            *(float4*)cp       = make_float4(acc[i][0], acc[i][1], acc[i][2], acc[i][3]);
            *(float4*)(cp + 4) = make_float4(acc[i][4], acc[i][5], acc[i][6], acc[i][7]);
        }
    }
}

// ------------------------- alpha dots, layer 1 (warp per row, fp16 xw) ---------
__global__ void __launch_bounds__(256) k_alpha1(const float* __restrict__ asrc,
                                                const float* __restrict__ adst, int n)
{
    int w = (blockIdx.x * blockDim.x + threadIdx.x) >> 5;
    int l = threadIdx.x & 31;
    if (w >= n) return;
    const uint2* xr = (const uint2*)(g_xw1h + (size_t)w * F1);
    float4 x1 = h4f(xr[l]), x2 = h4f(xr[32 + l]);
    float4 s1 = ((const float4*)asrc)[l], s2 = ((const float4*)asrc)[32 + l];
    float4 d1 = ((const float4*)adst)[l], d2 = ((const float4*)adst)[32 + l];
    float ps1 = x1.x*s1.x + x1.y*s1.y + x1.z*s1.z + x1.w*s1.w;
    float ps2 = x2.x*s2.x + x2.y*s2.y + x2.z*s2.z + x2.w*s2.w;
    float pd1 = x1.x*d1.x + x1.y*d1.y + x1.z*d1.z + x1.w*d1.w;
    float pd2 = x2.x*d2.x + x2.y*d2.y + x2.z*d2.z + x2.w*d2.w;
#pragma unroll
    for (int off = 8; off; off >>= 1) {
        ps1 += __shfl_xor_sync(0xffffffffu, ps1, off);
        ps2 += __shfl_xor_sync(0xffffffffu, ps2, off);
        pd1 += __shfl_xor_sync(0xffffffffu, pd1, off);
        pd2 += __shfl_xor_sync(0xffffffffu, pd2, off);
    }
    if (l == 0)  { g_as1[w*4+0] = ps1; g_as1[w*4+2] = ps2; g_ad1[w*4+0] = pd1; g_ad1[w*4+2] = pd2; }
    if (l == 16) { g_as1[w*4+1] = ps1; g_as1[w*4+3] = ps2; g_ad1[w*4+1] = pd1; g_ad1[w*4+3] = pd2; }
}

// ------------------------- alpha dots, layer 2 (warp per row) -------------------
__global__ void __launch_bounds__(256) k_alpha2(const float* __restrict__ asrc,
                                                const float* __restrict__ adst, int n)
{
    int w = (blockIdx.x * blockDim.x + threadIdx.x) >> 5;
    int l = threadIdx.x & 31;
    if (w >= n) return;
    float x0 = g_xw2[(size_t)w * HID + l];
    float x1 = g_xw2[(size_t)w * HID + 32 + l];
    float p = x0 * asrc[l] + x1 * asrc[32 + l];
    float q = x0 * adst[l] + x1 * adst[32 + l];
#pragma unroll
    for (int off = 16; off; off >>= 1) {
        p += __shfl_xor_sync(0xffffffffu, p, off);
        q += __shfl_xor_sync(0xffffffffu, q, off);
    }
    if (l == 0) { g_as2[w] = p; g_ad2[w] = q; }
}

// ------------------------- CSR build -------------------------
__global__ void k_count(const int* __restrict__ ei, int e, int etot) {
    int i = blockIdx.x * blockDim.x + threadIdx.x;
    if (i >= etot) return;
    int d = (i < e) ? ei[e + i] : (i - e);
    atomicAdd(&g_cur[d], 1);
}

// 3-phase scan: per-block scan (1024 elems/block) -> scan of block sums -> add
__global__ void __launch_bounds__(256) k_scanA(int n) {
    __shared__ int sh[256];
    int b = blockIdx.x, t = threadIdx.x;
    int base = b * 1024 + t * 4;
    int4 v = make_int4(0, 0, 0, 0);
    if (base + 3 < n) v = *(const int4*)(g_cur + base);
    else {
        if (base     < n) v.x = g_cur[base];
        if (base + 1 < n) v.y = g_cur[base + 1];
        if (base + 2 < n) v.z = g_cur[base + 2];
    }
    int s = v.x + v.y + v.z + v.w;
    sh[t] = s;
    __syncthreads();
    for (int off = 1; off < 256; off <<= 1) {
        int u = (t >= off) ? sh[t - off] : 0;
        __syncthreads();
        sh[t] += u;
        __syncthreads();
    }
    int excl = sh[t] - s;
    if (t == 255) g_bsum[b] = sh[255];
    int4 o;
    o.x = excl; o.y = o.x + v.x; o.z = o.y + v.y; o.w = o.z + v.z;
    if (base + 3 < n) *(int4*)(g_off + base) = o;
    else {
        if (base     < n) g_off[base]     = o.x;
        if (base + 1 < n) g_off[base + 1] = o.y;
        if (base + 2 < n) g_off[base + 2] = o.z;
    }
}

__global__ void k_scanB(int nb) {
    __shared__ int sh[64];
    int t = threadIdx.x;
    int v = (t < nb) ? g_bsum[t] : 0;
    sh[t] = v;
    __syncthreads();
    for (int off = 1; off < 64; off <<= 1) {
        int u = (t >= off) ? sh[t - off] : 0;
        __syncthreads();
        sh[t] += u;
        __syncthreads();
    }
    if (t < nb) g_bpre[t] = sh[t] - v;
}

__global__ void k_scanC(int n, int etot) {
    int i = blockIdx.x * blockDim.x + threadIdx.x;
    if (i < n) {
        int v = g_off[i] + g_bpre[i >> 10];
        g_off[i] = v;
        g_cur[i] = v;
    }
    if (i == 0) g_off[n] = etot;
}

__global__ void k_scatter(const int* __restrict__ ei, int e, int etot) {
    int i = blockIdx.x * blockDim.x + threadIdx.x;
    if (i >= etot) return;
    int s, d;
    if (i < e) { s = ei[i]; d = ei[e + i]; } else { s = d = i - e; }
    int pos = atomicAdd(&g_cur[d], 1);
    g_csrc[pos] = s;
}

// ------------------------- GAT layer-1 aggregation (warp per dst node) ----------
__global__ void __launch_bounds__(256) k_agg1(const float* __restrict__ b1, int n) {
    int w = (blockIdx.x * blockDim.x + threadIdx.x) >> 5;
    int l = threadIdx.x & 31;
    if (w >= n) return;
    int start = g_off[w], end = g_off[w + 1];
    float4 adv = ((const float4*)g_ad1)[w];
    float ad0 = adv.x, ad1 = adv.y, ad2 = adv.z, ad3 = adv.w;

    float m0 = -3.402823466e38f, m1 = m0, m2 = m0, m3 = m0;
    for (int i = start + l; i < end; i += 32) {
        int s = g_csrc[i];
        float4 t = ((const float4*)g_as1)[s];
        m0 = fmaxf(m0, lrelu(t.x + ad0));
        m1 = fmaxf(m1, lrelu(t.y + ad1));
        m2 = fmaxf(m2, lrelu(t.z + ad2));
        m3 = fmaxf(m3, lrelu(t.w + ad3));
    }
#pragma unroll
    for (int off = 16; off; off >>= 1) {
        m0 = fmaxf(m0, __shfl_xor_sync(0xffffffffu, m0, off));
        m1 = fmaxf(m1, __shfl_xor_sync(0xffffffffu, m1, off));
        m2 = fmaxf(m2, __shfl_xor_sync(0xffffffffu, m2, off));
        m3 = fmaxf(m3, __shfl_xor_sync(0xffffffffu, m3, off));
    }

    float4 acc1 = make_float4(0.f, 0.f, 0.f, 0.f);
    float4 acc2 = make_float4(0.f, 0.f, 0.f, 0.f);
    float d0 = 0.f, d1 = 0.f, d2 = 0.f, d3 = 0.f;
    const float4* asv = (const float4*)g_as1;
    bool lo = (l < 16);
    int i = start;
    for (; i + 2 <= end; i += 2) {
        int s0 = g_csrc[i], s1 = g_csrc[i + 1];
        float4 t0 = asv[s0], t1 = asv[s1];
        const uint2* x0p = (const uint2*)(g_xw1h + (size_t)s0 * F1);
        const uint2* x1p = (const uint2*)(g_xw1h + (size_t)s1 * F1);
        float4 xa0 = h4f(x0p[l]), xb0 = h4f(x0p[32 + l]);
        float4 xa1 = h4f(x1p[l]), xb1 = h4f(x1p[32 + l]);
        float w00 = __expf(lrelu(t0.x + ad0) - m0), w01 = __expf(lrelu(t0.y + ad1) - m1);
        float w02 = __expf(lrelu(t0.z + ad2) - m2), w03 = __expf(lrelu(t0.w + ad3) - m3);
        float w10 = __expf(lrelu(t1.x + ad0) - m0), w11 = __expf(lrelu(t1.y + ad1) - m1);
        float w12 = __expf(lrelu(t1.z + ad2) - m2), w13 = __expf(lrelu(t1.w + ad3) - m3);
        d0 += w00 + w10; d1 += w01 + w11; d2 += w02 + w12; d3 += w03 + w13;
        float wa0 = lo ? w00 : w01, wb0 = lo ? w02 : w03;
        float wa1 = lo ? w10 : w11, wb1 = lo ? w12 : w13;
        acc1.x += xa0.x * wa0 + xa1.x * wa1;
        acc1.y += xa0.y * wa0 + xa1.y * wa1;
        acc1.z += xa0.z * wa0 + xa1.z * wa1;
        acc1.w += xa0.w * wa0 + xa1.w * wa1;
        acc2.x += xb0.x * wb0 + xb1.x * wb1;
        acc2.y += xb0.y * wb0 + xb1.y * wb1;
        acc2.z += xb0.z * wb0 + xb1.z * wb1;
        acc2.w += xb0.w * wb0 + xb1.w * wb1;
    }
    if (i < end) {
        int s0 = g_csrc[i];
        float4 t0 = asv[s0];
        const uint2* x0p = (const uint2*)(g_xw1h + (size_t)s0 * F1);
        float4 xa0 = h4f(x0p[l]), xb0 = h4f(x0p[32 + l]);
        float w00 = __expf(lrelu(t0.x + ad0) - m0), w01 = __expf(lrelu(t0.y + ad1) - m1);
        float w02 = __expf(lrelu(t0.z + ad2) - m2), w03 = __expf(lrelu(t0.w + ad3) - m3);
        d0 += w00; d1 += w01; d2 += w02; d3 += w03;
        float wa0 = lo ? w00 : w01, wb0 = lo ? w02 : w03;
        acc1.x += xa0.x * wa0; acc1.y += xa0.y * wa0;
        acc1.z += xa0.z * wa0; acc1.w += xa0.w * wa0;
        acc2.x += xb0.x * wb0; acc2.y += xb0.y * wb0;
        acc2.z += xb0.z * wb0; acc2.w += xb0.w * wb0;
    }
    float rda = 1.f / (lo ? d0 : d1);
    float rdb = 1.f / (lo ? d2 : d3);
    float4 bb1 = ((const float4*)b1)[l], bb2 = ((const float4*)b1)[32 + l];
    float4 o1, o2;
    o1.x = eluf(acc1.x * rda + bb1.x); o1.y = eluf(acc1.y * rda + bb1.y);
    o1.z = eluf(acc1.z * rda + bb1.z); o1.w = eluf(acc1.w * rda + bb1.w);
    o2.x = eluf(acc2.x * rdb + bb2.x); o2.y = eluf(acc2.y * rdb + bb2.y);
    o2.z = eluf(acc2.z * rdb + bb2.z); o2.w = eluf(acc2.w * rdb + bb2.w);
    float* outp = g_h2 + (size_t)w * F1;
    ((float4*)outp)[l] = o1;
    ((float4*)outp)[32 + l] = o2;
}

// ------------------------- GAT layer-2 aggregation (warp per dst node) ----------
__global__ void __launch_bounds__(256) k_agg2(const float* __restrict__ b2, int n) {
    int w = (blockIdx.x * blockDim.x + threadIdx.x) >> 5;
    int l = threadIdx.x & 31;
    if (w >= n) return;
    int start = g_off[w], end = g_off[w + 1];
    float adv = g_ad2[w];
    float m = -3.402823466e38f;
    for (int i = start + l; i < end; i += 32)
        m = fmaxf(m, lrelu(g_as2[g_csrc[i]] + adv));
#pragma unroll
    for (int off = 16; off; off >>= 1)
        m = fmaxf(m, __shfl_xor_sync(0xffffffffu, m, off));

    float2 acc = make_float2(0.f, 0.f);
    float den = 0.f;
    int i = start;
    for (; i + 2 <= end; i += 2) {
        int s0 = g_csrc[i], s1 = g_csrc[i + 1];
        float e0 = __expf(lrelu(g_as2[s0] + adv) - m);
        float e1 = __expf(lrelu(g_as2[s1] + adv) - m);
        float2 x0 = ((const float2*)(g_xw2 + (size_t)s0 * HID))[l];
        float2 x1 = ((const float2*)(g_xw2 + (size_t)s1 * HID))[l];
        den += e0 + e1;
        acc.x += x0.x * e0 + x1.x * e1;
        acc.y += x0.y * e0 + x1.y * e1;
    }
    if (i < end) {
        int s0 = g_csrc[i];
        float e0 = __expf(lrelu(g_as2[s0] + adv) - m);
        float2 x0 = ((const float2*)(g_xw2 + (size_t)s0 * HID))[l];
        den += e0;
        acc.x += x0.x * e0;
        acc.y += x0.y * e0;
    }
    float r = 1.f / den;
    float2 bb = ((const float2*)b2)[l];
    float2 o;
    o.x = eluf(acc.x * r + bb.x);
    o.y = eluf(acc.y * r + bb.y);
    ((float2*)(g_h3 + (size_t)w * HID))[l] = o;
}

// ------------------------- logits + block max (warp per row) --------------------
__global__ void __launch_bounds__(256) k_logits(const float* __restrict__ Wout,
                                                const float* __restrict__ bout,
                                                float* __restrict__ out, int n)
{
    __shared__ float sm[8];
    int wi = threadIdx.x >> 5;
    int l = threadIdx.x & 31;
    int row = blockIdx.x * 8 + wi;
    float lg = -3.402823466e38f;
    if (row < n) {
        float2 hv = ((const float2*)(g_h3 + (size_t)row * HID))[l];
        float2 wv = ((const float2*)Wout)[l];
        float p = hv.x * wv.x + hv.y * wv.y;
#pragma unroll
        for (int off = 16; off; off >>= 1) p += __shfl_xor_sync(0xffffffffu, p, off);
        lg = p + bout[0];
        if (l == 0) out[n + row] = lg;
    }
    if (l == 0) sm[wi] = lg;
    __syncthreads();
    if (threadIdx.x == 0) {
        float mx = sm[0];
#pragma unroll
        for (int k = 1; k < 8; k++) mx = fmaxf(mx, sm[k]);
        unsigned u = __float_as_uint(mx);
        u = (u & 0x80000000u) ? ~u : (u | 0x80000000u);
        atomicMax(&g_maxbits, u);
    }
}

__global__ void k_expsum(const float* __restrict__ out, int n) {
    __shared__ float sm[256];
    float M = dec_max(g_maxbits);
    float s = 0.f;
    for (int i = blockIdx.x * blockDim.x + threadIdx.x; i < n; i += gridDim.x * blockDim.x)
        s += __expf(out[n + i] - M);
    sm[threadIdx.x] = s;
    __syncthreads();
    for (int off = 128; off; off >>= 1) {
        if (threadIdx.x < off) sm[threadIdx.x] += sm[threadIdx.x + off];
        __syncthreads();
    }
    if (threadIdx.x == 0) atomicAdd(&g_sumexp, sm[0]);
}

__global__ void k_weights(float* __restrict__ out, int n) {
    int i = blockIdx.x * blockDim.x + threadIdx.x;
    if (i >= n) return;
    float M = dec_max(g_maxbits);
    float S = g_sumexp;
    out[i] = __expf(out[n + i] - M) / S;
}

// ------------------------- launch -------------------------
extern "C" void kernel_launch(void* const* d_in, const int* in_sizes, int n_in,
                              void* d_out, int out_size)
{
    const float* x    = (const float*)d_in[0];
    const int*   ei   = (const int*)d_in[1];
    const float* reg  = (const float*)d_in[2];
    const float* ng   = (const float*)d_in[3];
    const float* nb   = (const float*)d_in[4];
    const float* rg   = (const float*)d_in[5];
    const float* rb   = (const float*)d_in[6];
    const float* W1   = (const float*)d_in[7];
    const float* as1  = (const float*)d_in[8];
    const float* ad1  = (const float*)d_in[9];
    const float* b1   = (const float*)d_in[10];
    const float* W2   = (const float*)d_in[11];
    const float* as2  = (const float*)d_in[12];
    const float* ad2  = (const float*)d_in[13];
    const float* b2   = (const float*)d_in[14];
    const float* Wout = (const float*)d_in[15];
    const float* bout = (const float*)d_in[16];
    float* out = (float*)d_out;

    int n = in_sizes[0] / FIN;
    int e = in_sizes[1] / 2;
    int etot = e + n;
    int wb = (n + 7) / 8;           // warp-per-row grids (8 warps / 256-thread block)
    int nbScan = (n + 1023) / 1024;

    k_init<<<(n + 255) / 256, 256>>>(n);
    k_rownorm<<<wb, 256>>>(x, ng, nb, n);
    k_cvec<<<1, 256>>>(reg, rg, rb, W1);

    // GEMM1: xw1h[n,256] = xn[n,128] @ W1[0:128,:] + cvec  (half output)
    dim3 g1(F1 / 128, (n + 127) / 128);
    k_gemm<0, 128, 128><<<g1, 256>>>(W1, n, F1, FIN);

    k_alpha1<<<wb, 256>>>(as1, ad1, n);

    // CSR build (by destination)
    k_count<<<(etot + 255) / 256, 256>>>(ei, e, etot);
    k_scanA<<<nbScan, 256>>>(n);
    k_scanB<<<1, 64>>>(nbScan);
    k_scanC<<<(n + 255) / 256, 256>>>(n, etot);
    k_scatter<<<(etot + 255) / 256, 256>>>(ei, e, etot);

    k_agg1<<<wb, 256>>>(b1, n);

    // GEMM2: xw2[n,64] = h2[n,256] @ W2[256,64]  (fp32 output)
    dim3 g2(1, (n + 255) / 256);
    k_gemm<1, 256, 64><<<g2, 256>>>(W2, n, HID, F1);

    k_alpha2<<<wb, 256>>>(as2, ad2, n);
    k_agg2<<<wb, 256>>>(b2, n);

    k_logits<<<wb, 256>>>(Wout, bout, out, n);
    k_expsum<<<256, 256>>>(out, n);
    k_weights<<<(n + 255) / 256, 256>>>(out, n);
}

// round 4
// speedup vs baseline: 1.5643x; 1.3422x over previous
#include <cuda_runtime.h>
#include <cuda_fp16.h>
#include <cstdint>

#define N_MAX 50000
#define E_MAX 1600000
#define ET_MAX (N_MAX + E_MAX)
#define FIN 128
#define F1 256
#define HID 64

#define NEG_SLOPE 0.2f
#define LN_EPS 1e-5f

// ------------------------- scratch (device globals; no allocation) ----------
__device__ __half g_xnh[(size_t)N_MAX * FIN];    // normalized node features (fp16)
__device__ __half g_w1t[(size_t)F1 * FIN];       // W1[0:128,:]^T  [256][128] fp16
__device__ __half g_w2t[(size_t)HID * F1];       // W2^T           [64][256]  fp16
__device__ __half g_xw1h[(size_t)N_MAX * F1];    // layer-1 projected (fp16)
__device__ float  g_as1[N_MAX * 4];
__device__ float  g_ad1[N_MAX * 4];
__device__ __half g_h2h[(size_t)N_MAX * F1];     // layer-1 output (ELU, fp16)
__device__ __half g_xw2h[(size_t)N_MAX * HID];   // layer-2 projected (fp16)
__device__ float  g_as2[N_MAX];
__device__ float  g_ad2[N_MAX];
__device__ float  g_h3[(size_t)N_MAX * HID];     // layer-2 output (ELU)
__device__ int    g_off[N_MAX + 1];              // CSR offsets (by dst)
__device__ int    g_cur[N_MAX];                  // degree counts / cursors
__device__ int    g_csrc[ET_MAX];                // CSR src node ids
__device__ float  g_cvec[F1];                    // regime contribution bias
__device__ int    g_bsum[64];                    // scan block totals
__device__ int    g_bpre[64];                    // scan block prefixes
__device__ unsigned g_maxbits;                   // encoded global max (softmax)
__device__ float  g_sumexp;

static __device__ __forceinline__ float lrelu(float x) { return x > 0.f ? x : NEG_SLOPE * x; }
static __device__ __forceinline__ float eluf(float x)  { return x > 0.f ? x : (__expf(x) - 1.f); }
static __device__ __forceinline__ float dec_max(unsigned u) {
    return (u & 0x80000000u) ? __uint_as_float(u & 0x7fffffffu) : __uint_as_float(~u);
}
static __device__ __forceinline__ float4 h4f(uint2 u) {
    __half2 a = *(__half2*)&u.x;
    __half2 b = *(__half2*)&u.y;
    float2 fa = __half22float2(a), fb = __half22float2(b);
    return make_float4(fa.x, fa.y, fb.x, fb.y);
}

static __device__ __forceinline__ void ldsm4(unsigned* r, const void* p) {
    unsigned addr = (unsigned)__cvta_generic_to_shared(p);
    asm volatile("ldmatrix.sync.aligned.m8n8.x4.shared.b16 {%0,%1,%2,%3}, [%4];\n"
                 : "=r"(r[0]), "=r"(r[1]), "=r"(r[2]), "=r"(r[3]) : "r"(addr));
}
static __device__ __forceinline__ void mma16816(float* d, const unsigned* a, const unsigned* b) {
    asm volatile(
        "mma.sync.aligned.m16n8k16.row.col.f32.f16.f16.f32 "
        "{%0,%1,%2,%3}, {%4,%5,%6,%7}, {%8,%9}, {%0,%1,%2,%3};\n"
        : "+f"(d[0]), "+f"(d[1]), "+f"(d[2]), "+f"(d[3])
        : "r"(a[0]), "r"(a[1]), "r"(a[2]), "r"(a[3]), "r"(b[0]), "r"(b[1]));
}

// ------------------------- init -------------------------
__global__ void k_init(int n) {
    int i = blockIdx.x * blockDim.x + threadIdx.x;
    if (i < n) g_cur[i] = 0;
    if (i == 0) { g_maxbits = 0u; g_sumexp = 0.f; }
}

// ------------------------- row layernorm (warp per row) -> fp16 ----------------
__global__ void __launch_bounds__(256) k_rownorm(
    const float* __restrict__ x, const float* __restrict__ gamma,
    const float* __restrict__ beta, int n)
{
    int w = (blockIdx.x * blockDim.x + threadIdx.x) >> 5;
    int l = threadIdx.x & 31;
    if (w >= n) return;
    float4 v = ((const float4*)(x + (size_t)w * FIN))[l];
    float s  = v.x + v.y + v.z + v.w;
    float ss = v.x*v.x + v.y*v.y + v.z*v.z + v.w*v.w;
#pragma unroll
    for (int off = 16; off; off >>= 1) {
        s  += __shfl_xor_sync(0xffffffffu, s, off);
        ss += __shfl_xor_sync(0xffffffffu, ss, off);
    }
    float mu = s * (1.f / FIN);
    float var = ss * (1.f / FIN) - mu * mu;
    float rstd = rsqrtf(var + LN_EPS);
    float4 g = ((const float4*)gamma)[l];
    float4 b = ((const float4*)beta)[l];
    __half2 p0 = __floats2half2_rn((v.x - mu) * rstd * g.x + b.x,
                                   (v.y - mu) * rstd * g.y + b.y);
    __half2 p1 = __floats2half2_rn((v.z - mu) * rstd * g.z + b.z,
                                   (v.w - mu) * rstd * g.w + b.w);
    uint2 u; u.x = *(unsigned*)&p0; u.y = *(unsigned*)&p1;
    *(uint2*)(g_xnh + (size_t)w * FIN + 4 * l) = u;
}

// ------------------------- weight transposes to fp16 ----------------------------
__global__ void k_prepW(const float* __restrict__ W1, const float* __restrict__ W2) {
    int i = blockIdx.x * blockDim.x + threadIdx.x;
    if (i < F1 * FIN) {
        int nn = i >> 7, kk = i & 127;          // w1t[n][k] = W1[k][n]
        g_w1t[i] = __float2half(W1[(size_t)kk * F1 + nn]);
    } else {
        int j = i - F1 * FIN;
        if (j < HID * F1) {
            int nn = j >> 8, kk = j & 255;      // w2t[n][k] = W2[k][n]
            g_w2t[j] = __float2half(W2[(size_t)kk * HID + nn]);
        }
    }
}

// ------------------------- regime LN + fold into per-column bias ----------------
__global__ void k_cvec(const float* __restrict__ reg, const float* __restrict__ rg,
                       const float* __restrict__ rb, const float* __restrict__ W1)
{
    __shared__ float rn[16];
    int t = threadIdx.x;
    if (t == 0) {
        float s = 0.f;
        for (int k = 0; k < 16; k++) s += reg[k];
        float mu = s * (1.f / 16.f);
        float ss = 0.f;
        for (int k = 0; k < 16; k++) { float d = reg[k] - mu; ss += d * d; }
        float rstd = rsqrtf(ss * (1.f / 16.f) + LN_EPS);
        for (int k = 0; k < 16; k++) rn[k] = (reg[k] - mu) * rstd * rg[k] + rb[k];
    }
    __syncthreads();
    if (t < F1) {
        float s = 0.f;
#pragma unroll
        for (int k = 0; k < 16; k++) s += rn[k] * W1[(size_t)(FIN + k) * F1 + t];
        g_cvec[t] = s;
    }
}

// ------------------------- tensor-core HGEMM (mma.m16n8k16) ---------------------
// SEL=0: xnh[n,128] @ w1t^T -> xw1h[n,256] + cvec
// SEL=1: h2h[n,256] @ w2t^T -> xw2h[n,64]
template <int SEL, int BM, int BN, int BK, int WM, int WN>
__global__ void __launch_bounds__(256) k_hgemm(int M, int K) {
    const __half* Ag = (SEL == 0) ? g_xnh : g_h2h;
    const __half* Bg = (SEL == 0) ? g_w1t : g_w2t;
    constexpr int LDSM = BK + 8;
    __shared__ __align__(16) __half As[BM][LDSM];
    __shared__ __align__(16) __half Bs[BN][LDSM];

    int tid = threadIdx.x;
    int wid = tid >> 5, lane = tid & 31;
    constexpr int NWN = BN / WN;
    int wm = wid / NWN, wn = wid % NWN;
    constexpr int MT = WM / 16, NT = WN / 8;
    int rb = blockIdx.y * BM, cb = blockIdx.x * BN;
    int lr = lane & 7, grp = lane >> 3;

    float acc[MT][NT][4];
#pragma unroll
    for (int mt = 0; mt < MT; mt++)
#pragma unroll
        for (int nt = 0; nt < NT; nt++)
#pragma unroll
            for (int q = 0; q < 4; q++) acc[mt][nt][q] = 0.f;

    for (int k0 = 0; k0 < K; k0 += BK) {
        constexpr int AV = BM * BK / 8;
#pragma unroll
        for (int s = tid; s < AV; s += 256) {
            int row = s / (BK / 8), seg = s % (BK / 8);
            uint4 v = make_uint4(0u, 0u, 0u, 0u);
            if (rb + row < M) v = *(const uint4*)(Ag + (size_t)(rb + row) * K + k0 + seg * 8);
            *(uint4*)&As[row][seg * 8] = v;
        }
        constexpr int BV = BN * BK / 8;
#pragma unroll
        for (int s = tid; s < BV; s += 256) {
            int row = s / (BK / 8), seg = s % (BK / 8);
            *(uint4*)&Bs[row][seg * 8] = *(const uint4*)(Bg + (size_t)(cb + row) * K + k0 + seg * 8);
        }
        __syncthreads();
#pragma unroll
        for (int kk = 0; kk < BK; kk += 16) {
            unsigned a[MT][4], b[NT][2];
#pragma unroll
            for (int mt = 0; mt < MT; mt++) {
                int r = wm * WM + mt * 16 + (grp & 1) * 8 + lr;
                int c = kk + (grp >> 1) * 8;
                ldsm4(a[mt], &As[r][c]);
            }
#pragma unroll
            for (int np = 0; np < NT; np += 2) {
                int r = wn * WN + np * 8 + (grp >> 1) * 8 + lr;
                int c = kk + (grp & 1) * 8;
                unsigned t[4];
                ldsm4(t, &Bs[r][c]);
                b[np][0] = t[0]; b[np][1] = t[1];
                b[np + 1][0] = t[2]; b[np + 1][1] = t[3];
            }
#pragma unroll
            for (int mt = 0; mt < MT; mt++)
#pragma unroll
                for (int nt = 0; nt < NT; nt++)
                    mma16816(acc[mt][nt], a[mt], b[nt]);
        }
        __syncthreads();
    }

    int qr = lane >> 2, qc = (lane & 3) * 2;
#pragma unroll
    for (int mt = 0; mt < MT; mt++)
#pragma unroll
        for (int nt = 0; nt < NT; nt++) {
            int row = rb + wm * WM + mt * 16 + qr;
            int col = cb + wn * WN + nt * 8 + qc;
            if (SEL == 0) {
                float2 cv = *(const float2*)(g_cvec + col);
                if (row < M)
                    *(__half2*)&g_xw1h[(size_t)row * F1 + col] =
                        __floats2half2_rn(acc[mt][nt][0] + cv.x, acc[mt][nt][1] + cv.y);
                if (row + 8 < M)
                    *(__half2*)&g_xw1h[(size_t)(row + 8) * F1 + col] =
                        __floats2half2_rn(acc[mt][nt][2] + cv.x, acc[mt][nt][3] + cv.y);
            } else {
                if (row < M)
                    *(__half2*)&g_xw2h[(size_t)row * HID + col] =
                        __floats2half2_rn(acc[mt][nt][0], acc[mt][nt][1]);
                if (row + 8 < M)
                    *(__half2*)&g_xw2h[(size_t)(row + 8) * HID + col] =
                        __floats2half2_rn(acc[mt][nt][2], acc[mt][nt][3]);
            }
        }
}

// ------------------------- alpha dots, layer 1 (warp per row, fp16 xw) ---------
__global__ void __launch_bounds__(256) k_alpha1(const float* __restrict__ asrc,
                                                const float* __restrict__ adst, int n)
{
    int w = (blockIdx.x * blockDim.x + threadIdx.x) >> 5;
    int l = threadIdx.x & 31;
    if (w >= n) return;
    const uint2* xr = (const uint2*)(g_xw1h + (size_t)w * F1);
    float4 x1 = h4f(xr[l]), x2 = h4f(xr[32 + l]);
    float4 s1 = ((const float4*)asrc)[l], s2 = ((const float4*)asrc)[32 + l];
    float4 d1 = ((const float4*)adst)[l], d2 = ((const float4*)adst)[32 + l];
    float ps1 = x1.x*s1.x + x1.y*s1.y + x1.z*s1.z + x1.w*s1.w;
    float ps2 = x2.x*s2.x + x2.y*s2.y + x2.z*s2.z + x2.w*s2.w;
    float pd1 = x1.x*d1.x + x1.y*d1.y + x1.z*d1.z + x1.w*d1.w;
    float pd2 = x2.x*d2.x + x2.y*d2.y + x2.z*d2.z + x2.w*d2.w;
#pragma unroll
    for (int off = 8; off; off >>= 1) {
        ps1 += __shfl_xor_sync(0xffffffffu, ps1, off);
        ps2 += __shfl_xor_sync(0xffffffffu, ps2, off);
        pd1 += __shfl_xor_sync(0xffffffffu, pd1, off);
        pd2 += __shfl_xor_sync(0xffffffffu, pd2, off);
    }
    if (l == 0)  { g_as1[w*4+0] = ps1; g_as1[w*4+2] = ps2; g_ad1[w*4+0] = pd1; g_ad1[w*4+2] = pd2; }
    if (l == 16) { g_as1[w*4+1] = ps1; g_as1[w*4+3] = ps2; g_ad1[w*4+1] = pd1; g_ad1[w*4+3] = pd2; }
}

// ------------------------- alpha dots, layer 2 (warp per row) -------------------
__global__ void __launch_bounds__(256) k_alpha2(const float* __restrict__ asrc,
                                                const float* __restrict__ adst, int n)
{
    int w = (blockIdx.x * blockDim.x + threadIdx.x) >> 5;
    int l = threadIdx.x & 31;
    if (w >= n) return;
    __half2 hx = *(const __half2*)&g_xw2h[(size_t)w * HID + 2 * l];
    float2 xf = __half22float2(hx);
    float2 sv = ((const float2*)asrc)[l];
    float2 dv = ((const float2*)adst)[l];
    float p = xf.x * sv.x + xf.y * sv.y;
    float q = xf.x * dv.x + xf.y * dv.y;
#pragma unroll
    for (int off = 16; off; off >>= 1) {
        p += __shfl_xor_sync(0xffffffffu, p, off);
        q += __shfl_xor_sync(0xffffffffu, q, off);
    }
    if (l == 0) { g_as2[w] = p; g_ad2[w] = q; }
}

// ------------------------- CSR build -------------------------
__global__ void k_count(const int* __restrict__ ei, int e, int etot) {
    int i = blockIdx.x * blockDim.x + threadIdx.x;
    if (i >= etot) return;
    int d = (i < e) ? ei[e + i] : (i - e);
    atomicAdd(&g_cur[d], 1);
}

__global__ void __launch_bounds__(256) k_scanA(int n) {
    __shared__ int sh[256];
    int b = blockIdx.x, t = threadIdx.x;
    int base = b * 1024 + t * 4;
    int4 v = make_int4(0, 0, 0, 0);
    if (base + 3 < n) v = *(const int4*)(g_cur + base);
    else {
        if (base     < n) v.x = g_cur[base];
        if (base + 1 < n) v.y = g_cur[base + 1];
        if (base + 2 < n) v.z = g_cur[base + 2];
    }
    int s = v.x + v.y + v.z + v.w;
    sh[t] = s;
    __syncthreads();
    for (int off = 1; off < 256; off <<= 1) {
        int u = (t >= off) ? sh[t - off] : 0;
        __syncthreads();
        sh[t] += u;
        __syncthreads();
    }
    int excl = sh[t] - s;
    if (t == 255) g_bsum[b] = sh[255];
    int4 o;
    o.x = excl; o.y = o.x + v.x; o.z = o.y + v.y; o.w = o.z + v.z;
    if (base + 3 < n) *(int4*)(g_off + base) = o;
    else {
        if (base     < n) g_off[base]     = o.x;
        if (base + 1 < n) g_off[base + 1] = o.y;
        if (base + 2 < n) g_off[base + 2] = o.z;
    }
}

__global__ void k_scanB(int nb) {
    __shared__ int sh[64];
    int t = threadIdx.x;
    int v = (t < nb) ? g_bsum[t] : 0;
    sh[t] = v;
    __syncthreads();
    for (int off = 1; off < 64; off <<= 1) {
        int u = (t >= off) ? sh[t - off] : 0;
        __syncthreads();
        sh[t] += u;
        __syncthreads();
    }
    if (t < nb) g_bpre[t] = sh[t] - v;
}

__global__ void k_scanC(int n, int etot) {
    int i = blockIdx.x * blockDim.x + threadIdx.x;
    if (i < n) {
        int v = g_off[i] + g_bpre[i >> 10];
        g_off[i] = v;
        g_cur[i] = v;
    }
    if (i == 0) g_off[n] = etot;
}

__global__ void k_scatter(const int* __restrict__ ei, int e, int etot) {
    int i = blockIdx.x * blockDim.x + threadIdx.x;
    if (i >= etot) return;
    int s, d;
    if (i < e) { s = ei[i]; d = ei[e + i]; } else { s = d = i - e; }
    int pos = atomicAdd(&g_cur[d], 1);
    g_csrc[pos] = s;
}

// ------------------------- GAT layer-1 aggregation (warp per dst node) ----------
__global__ void __launch_bounds__(256) k_agg1(const float* __restrict__ b1, int n) {
    int w = (blockIdx.x * blockDim.x + threadIdx.x) >> 5;
    int l = threadIdx.x & 31;
    if (w >= n) return;
    int start = g_off[w], end = g_off[w + 1];
    float4 adv = ((const float4*)g_ad1)[w];
    float ad0 = adv.x, ad1 = adv.y, ad2 = adv.z, ad3 = adv.w;

    float m0 = -3.402823466e38f, m1 = m0, m2 = m0, m3 = m0;
    for (int i = start + l; i < end; i += 32) {
        int s = g_csrc[i];
        float4 t = ((const float4*)g_as1)[s];
        m0 = fmaxf(m0, lrelu(t.x + ad0));
        m1 = fmaxf(m1, lrelu(t.y + ad1));
        m2 = fmaxf(m2, lrelu(t.z + ad2));
        m3 = fmaxf(m3, lrelu(t.w + ad3));
    }
#pragma unroll
    for (int off = 16; off; off >>= 1) {
        m0 = fmaxf(m0, __shfl_xor_sync(0xffffffffu, m0, off));
        m1 = fmaxf(m1, __shfl_xor_sync(0xffffffffu, m1, off));
        m2 = fmaxf(m2, __shfl_xor_sync(0xffffffffu, m2, off));
        m3 = fmaxf(m3, __shfl_xor_sync(0xffffffffu, m3, off));
    }

    float4 acc1 = make_float4(0.f, 0.f, 0.f, 0.f);
    float4 acc2 = make_float4(0.f, 0.f, 0.f, 0.f);
    float d0 = 0.f, d1 = 0.f, d2 = 0.f, d3 = 0.f;
    const float4* asv = (const float4*)g_as1;
    bool lo = (l < 16);
    int i = start;
    for (; i + 2 <= end; i += 2) {
        int s0 = g_csrc[i], s1 = g_csrc[i + 1];
        float4 t0 = asv[s0], t1 = asv[s1];
        const uint2* x0p = (const uint2*)(g_xw1h + (size_t)s0 * F1);
        const uint2* x1p = (const uint2*)(g_xw1h + (size_t)s1 * F1);
        float4 xa0 = h4f(x0p[l]), xb0 = h4f(x0p[32 + l]);
        float4 xa1 = h4f(x1p[l]), xb1 = h4f(x1p[32 + l]);
        float w00 = __expf(lrelu(t0.x + ad0) - m0), w01 = __expf(lrelu(t0.y + ad1) - m1);
        float w02 = __expf(lrelu(t0.z + ad2) - m2), w03 = __expf(lrelu(t0.w + ad3) - m3);
        float w10 = __expf(lrelu(t1.x + ad0) - m0), w11 = __expf(lrelu(t1.y + ad1) - m1);
        float w12 = __expf(lrelu(t1.z + ad2) - m2), w13 = __expf(lrelu(t1.w + ad3) - m3);
        d0 += w00 + w10; d1 += w01 + w11; d2 += w02 + w12; d3 += w03 + w13;
        float wa0 = lo ? w00 : w01, wb0 = lo ? w02 : w03;
        float wa1 = lo ? w10 : w11, wb1 = lo ? w12 : w13;
        acc1.x += xa0.x * wa0 + xa1.x * wa1;
        acc1.y += xa0.y * wa0 + xa1.y * wa1;
        acc1.z += xa0.z * wa0 + xa1.z * wa1;
        acc1.w += xa0.w * wa0 + xa1.w * wa1;
        acc2.x += xb0.x * wb0 + xb1.x * wb1;
        acc2.y += xb0.y * wb0 + xb1.y * wb1;
        acc2.z += xb0.z * wb0 + xb1.z * wb1;
        acc2.w += xb0.w * wb0 + xb1.w * wb1;
    }
    if (i < end) {
        int s0 = g_csrc[i];
        float4 t0 = asv[s0];
        const uint2* x0p = (const uint2*)(g_xw1h + (size_t)s0 * F1);
        float4 xa0 = h4f(x0p[l]), xb0 = h4f(x0p[32 + l]);
        float w00 = __expf(lrelu(t0.x + ad0) - m0), w01 = __expf(lrelu(t0.y + ad1) - m1);
        float w02 = __expf(lrelu(t0.z + ad2) - m2), w03 = __expf(lrelu(t0.w + ad3) - m3);
        d0 += w00; d1 += w01; d2 += w02; d3 += w03;
        float wa0 = lo ? w00 : w01, wb0 = lo ? w02 : w03;
        acc1.x += xa0.x * wa0; acc1.y += xa0.y * wa0;
        acc1.z += xa0.z * wa0; acc1.w += xa0.w * wa0;
        acc2.x += xb0.x * wb0; acc2.y += xb0.y * wb0;
        acc2.z += xb0.z * wb0; acc2.w += xb0.w * wb0;
    }
    float rda = 1.f / (lo ? d0 : d1);
    float rdb = 1.f / (lo ? d2 : d3);
    float4 bb1 = ((const float4*)b1)[l], bb2 = ((const float4*)b1)[32 + l];
    __half2 p0 = __floats2half2_rn(eluf(acc1.x * rda + bb1.x), eluf(acc1.y * rda + bb1.y));
    __half2 p1 = __floats2half2_rn(eluf(acc1.z * rda + bb1.z), eluf(acc1.w * rda + bb1.w));
    __half2 p2 = __floats2half2_rn(eluf(acc2.x * rdb + bb2.x), eluf(acc2.y * rdb + bb2.y));
    __half2 p3 = __floats2half2_rn(eluf(acc2.z * rdb + bb2.z), eluf(acc2.w * rdb + bb2.w));
    uint2 u1; u1.x = *(unsigned*)&p0; u1.y = *(unsigned*)&p1;
    uint2 u2; u2.x = *(unsigned*)&p2; u2.y = *(unsigned*)&p3;
    __half* outp = g_h2h + (size_t)w * F1;
    *(uint2*)(outp + 4 * l) = u1;
    *(uint2*)(outp + 128 + 4 * l) = u2;
}

// ------------------------- GAT layer-2 aggregation (warp per dst node) ----------
__global__ void __launch_bounds__(256) k_agg2(const float* __restrict__ b2, int n) {
    int w = (blockIdx.x * blockDim.x + threadIdx.x) >> 5;
    int l = threadIdx.x & 31;
    if (w >= n) return;
    int start = g_off[w], end = g_off[w + 1];
    float adv = g_ad2[w];
    float m = -3.402823466e38f;
    for (int i = start + l; i < end; i += 32)
        m = fmaxf(m, lrelu(g_as2[g_csrc[i]] + adv));
#pragma unroll
    for (int off = 16; off; off >>= 1)
        m = fmaxf(m, __shfl_xor_sync(0xffffffffu, m, off));

    float2 acc = make_float2(0.f, 0.f);
    float den = 0.f;
    int i = start;
    for (; i + 2 <= end; i += 2) {
        int s0 = g_csrc[i], s1 = g_csrc[i + 1];
        float e0 = __expf(lrelu(g_as2[s0] + adv) - m);
        float e1 = __expf(lrelu(g_as2[s1] + adv) - m);
        float2 x0 = __half22float2(*(const __half2*)&g_xw2h[(size_t)s0 * HID + 2 * l]);
        float2 x1 = __half22float2(*(const __half2*)&g_xw2h[(size_t)s1 * HID + 2 * l]);
        den += e0 + e1;
        acc.x += x0.x * e0 + x1.x * e1;
        acc.y += x0.y * e0 + x1.y * e1;
    }
    if (i < end) {
        int s0 = g_csrc[i];
        float e0 = __expf(lrelu(g_as2[s0] + adv) - m);
        float2 x0 = __half22float2(*(const __half2*)&g_xw2h[(size_t)s0 * HID + 2 * l]);
        den += e0;
        acc.x += x0.x * e0;
        acc.y += x0.y * e0;
    }
    float r = 1.f / den;
    float2 bb = ((const float2*)b2)[l];
    float2 o;
    o.x = eluf(acc.x * r + bb.x);
    o.y = eluf(acc.y * r + bb.y);
    *(float2*)(g_h3 + (size_t)w * HID + 2 * l) = o;
}

// ------------------------- logits + block max (warp per row) --------------------
__global__ void __launch_bounds__(256) k_logits(const float* __restrict__ Wout,
                                                const float* __restrict__ bout,
                                                float* __restrict__ out, int n)
{
    __shared__ float sm[8];
    int wi = threadIdx.x >> 5;
    int l = threadIdx.x & 31;
    int row = blockIdx.x * 8 + wi;
    float lg = -3.402823466e38f;
    if (row < n) {
        float2 hv = ((const float2*)(g_h3 + (size_t)row * HID))[l];
        float2 wv = ((const float2*)Wout)[l];
        float p = hv.x * wv.x + hv.y * wv.y;
#pragma unroll
        for (int off = 16; off; off >>= 1) p += __shfl_xor_sync(0xffffffffu, p, off);
        lg = p + bout[0];
        if (l == 0) out[n + row] = lg;
    }
    if (l == 0) sm[wi] = lg;
    __syncthreads();
    if (threadIdx.x == 0) {
        float mx = sm[0];
#pragma unroll
        for (int k = 1; k < 8; k++) mx = fmaxf(mx, sm[k]);
        unsigned u = __float_as_uint(mx);
        u = (u & 0x80000000u) ? ~u : (u | 0x80000000u);
        atomicMax(&g_maxbits, u);
    }
}

__global__ void k_expsum(const float* __restrict__ out, int n) {
    __shared__ float sm[256];
    float M = dec_max(g_maxbits);
    float s = 0.f;
    for (int i = blockIdx.x * blockDim.x + threadIdx.x; i < n; i += gridDim.x * blockDim.x)
        s += __expf(out[n + i] - M);
    sm[threadIdx.x] = s;
    __syncthreads();
    for (int off = 128; off; off >>= 1) {
        if (threadIdx.x < off) sm[threadIdx.x] += sm[threadIdx.x + off];
        __syncthreads();
    }
    if (threadIdx.x == 0) atomicAdd(&g_sumexp, sm[0]);
}

__global__ void k_weights(float* __restrict__ out, int n) {
    int i = blockIdx.x * blockDim.x + threadIdx.x;
    if (i >= n) return;
    float M = dec_max(g_maxbits);
    float S = g_sumexp;
    out[i] = __expf(out[n + i] - M) / S;
}

// ------------------------- launch -------------------------
extern "C" void kernel_launch(void* const* d_in, const int* in_sizes, int n_in,
                              void* d_out, int out_size)
{
    const float* x    = (const float*)d_in[0];
    const int*   ei   = (const int*)d_in[1];
    const float* reg  = (const float*)d_in[2];
    const float* ng   = (const float*)d_in[3];
    const float* nb   = (const float*)d_in[4];
    const float* rg   = (const float*)d_in[5];
    const float* rb   = (const float*)d_in[6];
    const float* W1   = (const float*)d_in[7];
    const float* as1  = (const float*)d_in[8];
    const float* ad1  = (const float*)d_in[9];
    const float* b1   = (const float*)d_in[10];
    const float* W2   = (const float*)d_in[11];
    const float* as2  = (const float*)d_in[12];
    const float* ad2  = (const float*)d_in[13];
    const float* b2   = (const float*)d_in[14];
    const float* Wout = (const float*)d_in[15];
    const float* bout = (const float*)d_in[16];
    float* out = (float*)d_out;

    int n = in_sizes[0] / FIN;
    int e = in_sizes[1] / 2;
    int etot = e + n;
    int wb = (n + 7) / 8;
    int nbScan = (n + 1023) / 1024;

    k_init<<<(n + 255) / 256, 256>>>(n);
    k_rownorm<<<wb, 256>>>(x, ng, nb, n);
    k_prepW<<<(F1 * FIN + HID * F1 + 255) / 256, 256>>>(W1, W2);
    k_cvec<<<1, 256>>>(reg, rg, rb, W1);

    // GEMM1: xw1h[n,256] = xnh[n,128] @ w1t^T + cvec (tensor cores)
    dim3 g1(2, (n + 127) / 128);
    k_hgemm<0, 128, 128, 64, 64, 32><<<g1, 256>>>(n, FIN);

    k_alpha1<<<wb, 256>>>(as1, ad1, n);

    // CSR build (by destination)
    k_count<<<(etot + 255) / 256, 256>>>(ei, e, etot);
    k_scanA<<<nbScan, 256>>>(n);
    k_scanB<<<1, 64>>>(nbScan);
    k_scanC<<<(n + 255) / 256, 256>>>(n, etot);
    k_scatter<<<(etot + 255) / 256, 256>>>(ei, e, etot);

    k_agg1<<<wb, 256>>>(b1, n);

    // GEMM2: xw2h[n,64] = h2h[n,256] @ w2t^T (tensor cores)
    dim3 g2(1, (n + 127) / 128);
    k_hgemm<1, 128, 64, 64, 32, 32><<<g2, 256>>>(n, F1);

    k_alpha2<<<wb, 256>>>(as2, ad2, n);
    k_agg2<<<wb, 256>>>(b2, n);

    k_logits<<<wb, 256>>>(Wout, bout, out, n);
    k_expsum<<<256, 256>>>(out, n);
    k_weights<<<(n + 255) / 256, 256>>>(out, n);
}

// round 5
// speedup vs baseline: 1.8783x; 1.2007x over previous
#include <cuda_runtime.h>
#include <cuda_fp16.h>
#include <cstdint>

#define N_MAX 50000
#define E_MAX 1600000
#define ET_MAX (N_MAX + E_MAX)
#define FIN 128
#define F1 256
#define HID 64

#define NEG_SLOPE 0.2f
#define LN_EPS 1e-5f

// ------------------------- scratch (device globals; no allocation) ----------
__device__ __half g_xnh[(size_t)N_MAX * FIN];    // normalized node features (fp16)
__device__ __half g_w1t[(size_t)F1 * FIN];       // W1[0:128,:]^T  [256][128] fp16
__device__ __half g_w2t[(size_t)HID * F1];       // W2^T           [64][256]  fp16
__device__ __half g_xw1h[(size_t)N_MAX * F1];    // layer-1 projected (fp16)
__device__ float  g_as1[N_MAX * 4];
__device__ float  g_ad1[N_MAX * 4];
__device__ __half g_h2h[(size_t)N_MAX * F1];     // layer-1 output (ELU, fp16)
__device__ __half g_xw2h[(size_t)N_MAX * HID];   // layer-2 projected (fp16)
__device__ float  g_as2[N_MAX];
__device__ float  g_ad2[N_MAX];
__device__ float  g_h3[(size_t)N_MAX * HID];     // layer-2 output (ELU)
__device__ int    g_off[N_MAX + 1];              // CSR offsets (by dst)
__device__ int    g_cur[N_MAX];                  // degree counts / cursors
__device__ int    g_csrc[ET_MAX];                // CSR src node ids
__device__ float  g_cvec[F1];                    // regime contribution bias
__device__ int    g_bsum[64];                    // scan block totals
__device__ int    g_bpre[64];                    // scan block prefixes
__device__ unsigned g_emax[10];                  // encoded per-head alpha maxes
                                                 // 0-3: max as1 (heads), 4-7: max ad1, 8: as2, 9: ad2
__device__ unsigned g_maxbits;                   // encoded global max (softmax)
__device__ float  g_sumexp;

static __device__ __forceinline__ float lrelu(float x) { return x > 0.f ? x : NEG_SLOPE * x; }
static __device__ __forceinline__ float eluf(float x)  { return x > 0.f ? x : (__expf(x) - 1.f); }
static __device__ __forceinline__ unsigned encf(float x) {
    unsigned u = __float_as_uint(x);
    return (u & 0x80000000u) ? ~u : (u | 0x80000000u);
}
static __device__ __forceinline__ float dec_max(unsigned u) {
    return (u & 0x80000000u) ? __uint_as_float(u & 0x7fffffffu) : __uint_as_float(~u);
}
static __device__ __forceinline__ float4 h4f(uint2 u) {
    __half2 a = *(__half2*)&u.x;
    __half2 b = *(__half2*)&u.y;
    float2 fa = __half22float2(a), fb = __half22float2(b);
    return make_float4(fa.x, fa.y, fb.x, fb.y);
}

static __device__ __forceinline__ void ldsm4(unsigned* r, const void* p) {
    unsigned addr = (unsigned)__cvta_generic_to_shared(p);
    asm volatile("ldmatrix.sync.aligned.m8n8.x4.shared.b16 {%0,%1,%2,%3}, [%4];\n"
                 : "=r"(r[0]), "=r"(r[1]), "=r"(r[2]), "=r"(r[3]) : "r"(addr));
}
static __device__ __forceinline__ void mma16816(float* d, const unsigned* a, const unsigned* b) {
    asm volatile(
        "mma.sync.aligned.m16n8k16.row.col.f32.f16.f16.f32 "
        "{%0,%1,%2,%3}, {%4,%5,%6,%7}, {%8,%9}, {%0,%1,%2,%3};\n"
        : "+f"(d[0]), "+f"(d[1]), "+f"(d[2]), "+f"(d[3])
        : "r"(a[0]), "r"(a[1]), "r"(a[2]), "r"(b[0]), "r"(a[3]), "r"(b[1]));
}
// NOTE: operand order must match PTX spec {a0,a1,a2,a3},{b0,b1}; fix below.
static __device__ __forceinline__ void mma16816f(float* d, const unsigned* a, const unsigned* b) {
    asm volatile(
        "mma.sync.aligned.m16n8k16.row.col.f32.f16.f16.f32 "
        "{%0,%1,%2,%3}, {%4,%5,%6,%7}, {%8,%9}, {%0,%1,%2,%3};\n"
        : "+f"(d[0]), "+f"(d[1]), "+f"(d[2]), "+f"(d[3])
        : "r"(a[0]), "r"(a[1]), "r"(a[2]), "r"(a[3]), "r"(b[0]), "r"(b[1]));
}

// ------------------------- init -------------------------
__global__ void k_init(int n) {
    int i = blockIdx.x * blockDim.x + threadIdx.x;
    if (i < n) g_cur[i] = 0;
    if (i < 10) g_emax[i] = 0u;
    if (i == 0) { g_maxbits = 0u; g_sumexp = 0.f; }
}

// ------------------------- row layernorm (warp per row) -> fp16 ----------------
__global__ void __launch_bounds__(256) k_rownorm(
    const float* __restrict__ x, const float* __restrict__ gamma,
    const float* __restrict__ beta, int n)
{
    int w = (blockIdx.x * blockDim.x + threadIdx.x) >> 5;
    int l = threadIdx.x & 31;
    if (w >= n) return;
    float4 v = ((const float4*)(x + (size_t)w * FIN))[l];
    float s  = v.x + v.y + v.z + v.w;
    float ss = v.x*v.x + v.y*v.y + v.z*v.z + v.w*v.w;
#pragma unroll
    for (int off = 16; off; off >>= 1) {
        s  += __shfl_xor_sync(0xffffffffu, s, off);
        ss += __shfl_xor_sync(0xffffffffu, ss, off);
    }
    float mu = s * (1.f / FIN);
    float var = ss * (1.f / FIN) - mu * mu;
    float rstd = rsqrtf(var + LN_EPS);
    float4 g = ((const float4*)gamma)[l];
    float4 b = ((const float4*)beta)[l];
    __half2 p0 = __floats2half2_rn((v.x - mu) * rstd * g.x + b.x,
                                   (v.y - mu) * rstd * g.y + b.y);
    __half2 p1 = __floats2half2_rn((v.z - mu) * rstd * g.z + b.z,
                                   (v.w - mu) * rstd * g.w + b.w);
    uint2 u; u.x = *(unsigned*)&p0; u.y = *(unsigned*)&p1;
    *(uint2*)(g_xnh + (size_t)w * FIN + 4 * l) = u;
}

// ------------------------- weight transposes to fp16 ----------------------------
__global__ void k_prepW(const float* __restrict__ W1, const float* __restrict__ W2) {
    int i = blockIdx.x * blockDim.x + threadIdx.x;
    if (i < F1 * FIN) {
        int nn = i >> 7, kk = i & 127;          // w1t[n][k] = W1[k][n]
        g_w1t[i] = __float2half(W1[(size_t)kk * F1 + nn]);
    } else {
        int j = i - F1 * FIN;
        if (j < HID * F1) {
            int nn = j >> 8, kk = j & 255;      // w2t[n][k] = W2[k][n]
            g_w2t[j] = __float2half(W2[(size_t)kk * HID + nn]);
        }
    }
}

// ------------------------- regime LN + fold into per-column bias ----------------
__global__ void k_cvec(const float* __restrict__ reg, const float* __restrict__ rg,
                       const float* __restrict__ rb, const float* __restrict__ W1)
{
    __shared__ float rn[16];
    int t = threadIdx.x;
    if (t < 32) {
        float v = (t < 16) ? reg[t] : 0.f;
        float s = v, ss = v * v;
#pragma unroll
        for (int off = 16; off; off >>= 1) {
            s  += __shfl_xor_sync(0xffffffffu, s, off);
            ss += __shfl_xor_sync(0xffffffffu, ss, off);
        }
        float mu = s * (1.f / 16.f);
        float var = ss * (1.f / 16.f) - mu * mu;
        float rstd = rsqrtf(var + LN_EPS);
        if (t < 16) rn[t] = (v - mu) * rstd * rg[t] + rb[t];
    }
    __syncthreads();
    if (t < F1) {
        float s = 0.f;
#pragma unroll
        for (int k = 0; k < 16; k++) s += rn[k] * W1[(size_t)(FIN + k) * F1 + t];
        g_cvec[t] = s;
    }
}

// ------------------------- tensor-core HGEMM (mma.m16n8k16) ---------------------
template <int SEL, int BM, int BN, int BK, int WM, int WN>
__global__ void __launch_bounds__(256) k_hgemm(int M, int K) {
    const __half* Ag = (SEL == 0) ? g_xnh : g_h2h;
    const __half* Bg = (SEL == 0) ? g_w1t : g_w2t;
    constexpr int LDSM = BK + 8;
    __shared__ __align__(16) __half As[BM][LDSM];
    __shared__ __align__(16) __half Bs[BN][LDSM];

    int tid = threadIdx.x;
    int wid = tid >> 5, lane = tid & 31;
    constexpr int NWN = BN / WN;
    int wm = wid / NWN, wn = wid % NWN;
    constexpr int MT = WM / 16, NT = WN / 8;
    int rb = blockIdx.y * BM, cb = blockIdx.x * BN;
    int lr = lane & 7, grp = lane >> 3;

    float acc[MT][NT][4];
#pragma unroll
    for (int mt = 0; mt < MT; mt++)
#pragma unroll
        for (int nt = 0; nt < NT; nt++)
#pragma unroll
            for (int q = 0; q < 4; q++) acc[mt][nt][q] = 0.f;

    for (int k0 = 0; k0 < K; k0 += BK) {
        constexpr int AV = BM * BK / 8;
#pragma unroll
        for (int s = tid; s < AV; s += 256) {
            int row = s / (BK / 8), seg = s % (BK / 8);
            uint4 v = make_uint4(0u, 0u, 0u, 0u);
            if (rb + row < M) v = *(const uint4*)(Ag + (size_t)(rb + row) * K + k0 + seg * 8);
            *(uint4*)&As[row][seg * 8] = v;
        }
        constexpr int BV = BN * BK / 8;
#pragma unroll
        for (int s = tid; s < BV; s += 256) {
            int row = s / (BK / 8), seg = s % (BK / 8);
            *(uint4*)&Bs[row][seg * 8] = *(const uint4*)(Bg + (size_t)(cb + row) * K + k0 + seg * 8);
        }
        __syncthreads();
#pragma unroll
        for (int kk = 0; kk < BK; kk += 16) {
            unsigned a[MT][4], b[NT][2];
#pragma unroll
            for (int mt = 0; mt < MT; mt++) {
                int r = wm * WM + mt * 16 + (grp & 1) * 8 + lr;
                int c = kk + (grp >> 1) * 8;
                ldsm4(a[mt], &As[r][c]);
            }
#pragma unroll
            for (int np = 0; np < NT; np += 2) {
                int r = wn * WN + np * 8 + (grp >> 1) * 8 + lr;
                int c = kk + (grp & 1) * 8;
                unsigned t[4];
                ldsm4(t, &Bs[r][c]);
                b[np][0] = t[0]; b[np][1] = t[1];
                b[np + 1][0] = t[2]; b[np + 1][1] = t[3];
            }
#pragma unroll
            for (int mt = 0; mt < MT; mt++)
#pragma unroll
                for (int nt = 0; nt < NT; nt++)
                    mma16816f(acc[mt][nt], a[mt], b[nt]);
        }
        __syncthreads();
    }

    int qr = lane >> 2, qc = (lane & 3) * 2;
#pragma unroll
    for (int mt = 0; mt < MT; mt++)
#pragma unroll
        for (int nt = 0; nt < NT; nt++) {
            int row = rb + wm * WM + mt * 16 + qr;
            int col = cb + wn * WN + nt * 8 + qc;
            if (SEL == 0) {
                float2 cv = *(const float2*)(g_cvec + col);
                if (row < M)
                    *(__half2*)&g_xw1h[(size_t)row * F1 + col] =
                        __floats2half2_rn(acc[mt][nt][0] + cv.x, acc[mt][nt][1] + cv.y);
                if (row + 8 < M)
                    *(__half2*)&g_xw1h[(size_t)(row + 8) * F1 + col] =
                        __floats2half2_rn(acc[mt][nt][2] + cv.x, acc[mt][nt][3] + cv.y);
            } else {
                if (row < M)
                    *(__half2*)&g_xw2h[(size_t)row * HID + col] =
                        __floats2half2_rn(acc[mt][nt][0], acc[mt][nt][1]);
                if (row + 8 < M)
                    *(__half2*)&g_xw2h[(size_t)(row + 8) * HID + col] =
                        __floats2half2_rn(acc[mt][nt][2], acc[mt][nt][3]);
            }
        }
}

// ------------------- alpha dots, layer 1 + global per-head maxes ----------------
__global__ void __launch_bounds__(256) k_alpha1(const float* __restrict__ asrc,
                                                const float* __restrict__ adst, int n)
{
    __shared__ float smax[8][8];   // [slot][warp]
    int wi = threadIdx.x >> 5;
    int l = threadIdx.x & 31;
    int w = blockIdx.x * 8 + wi;
    const float NEGINF = -3.402823466e38f;
    float ps1 = NEGINF, ps2 = NEGINF, pd1 = NEGINF, pd2 = NEGINF;

    if (w < n) {
        const uint2* xr = (const uint2*)(g_xw1h + (size_t)w * F1);
        float4 x1 = h4f(xr[l]), x2 = h4f(xr[32 + l]);
        float4 s1 = ((const float4*)asrc)[l], s2 = ((const float4*)asrc)[32 + l];
        float4 d1 = ((const float4*)adst)[l], d2 = ((const float4*)adst)[32 + l];
        ps1 = x1.x*s1.x + x1.y*s1.y + x1.z*s1.z + x1.w*s1.w;
        ps2 = x2.x*s2.x + x2.y*s2.y + x2.z*s2.z + x2.w*s2.w;
        pd1 = x1.x*d1.x + x1.y*d1.y + x1.z*d1.z + x1.w*d1.w;
        pd2 = x2.x*d2.x + x2.y*d2.y + x2.z*d2.z + x2.w*d2.w;
#pragma unroll
        for (int off = 8; off; off >>= 1) {
            ps1 += __shfl_xor_sync(0xffffffffu, ps1, off);
            ps2 += __shfl_xor_sync(0xffffffffu, ps2, off);
            pd1 += __shfl_xor_sync(0xffffffffu, pd1, off);
            pd2 += __shfl_xor_sync(0xffffffffu, pd2, off);
        }
        if (l == 0)  { g_as1[w*4+0] = ps1; g_as1[w*4+2] = ps2; g_ad1[w*4+0] = pd1; g_ad1[w*4+2] = pd2; }
        if (l == 16) { g_as1[w*4+1] = ps1; g_as1[w*4+3] = ps2; g_ad1[w*4+1] = pd1; g_ad1[w*4+3] = pd2; }
    }
    if (l == 0)  { smax[0][wi] = ps1; smax[2][wi] = ps2; smax[4][wi] = pd1; smax[6][wi] = pd2; }
    if (l == 16) { smax[1][wi] = ps1; smax[3][wi] = ps2; smax[5][wi] = pd1; smax[7][wi] = pd2; }
    __syncthreads();
    if (threadIdx.x < 8) {
        float m = smax[threadIdx.x][0];
#pragma unroll
        for (int k = 1; k < 8; k++) m = fmaxf(m, smax[threadIdx.x][k]);
        if (m > NEGINF) atomicMax(&g_emax[threadIdx.x], encf(m));
    }
}

// ------------------- alpha dots, layer 2 + global maxes -------------------------
__global__ void __launch_bounds__(256) k_alpha2(const float* __restrict__ asrc,
                                                const float* __restrict__ adst, int n)
{
    __shared__ float smax[2][8];
    int wi = threadIdx.x >> 5;
    int l = threadIdx.x & 31;
    int w = blockIdx.x * 8 + wi;
    const float NEGINF = -3.402823466e38f;
    float p = NEGINF, q = NEGINF;
    if (w < n) {
        __half2 hx = *(const __half2*)&g_xw2h[(size_t)w * HID + 2 * l];
        float2 xf = __half22float2(hx);
        float2 sv = ((const float2*)asrc)[l];
        float2 dv = ((const float2*)adst)[l];
        p = xf.x * sv.x + xf.y * sv.y;
        q = xf.x * dv.x + xf.y * dv.y;
#pragma unroll
        for (int off = 16; off; off >>= 1) {
            p += __shfl_xor_sync(0xffffffffu, p, off);
            q += __shfl_xor_sync(0xffffffffu, q, off);
        }
        if (l == 0) { g_as2[w] = p; g_ad2[w] = q; }
    }
    if (l == 0) { smax[0][wi] = p; smax[1][wi] = q; }
    __syncthreads();
    if (threadIdx.x < 2) {
        float m = smax[threadIdx.x][0];
#pragma unroll
        for (int k = 1; k < 8; k++) m = fmaxf(m, smax[threadIdx.x][k]);
        if (m > NEGINF) atomicMax(&g_emax[8 + threadIdx.x], encf(m));
    }
}

// ------------------------- CSR build -------------------------
__global__ void k_count(const int* __restrict__ ei, int e, int etot) {
    int i = blockIdx.x * blockDim.x + threadIdx.x;
    if (i >= etot) return;
    int d = (i < e) ? ei[e + i] : (i - e);
    atomicAdd(&g_cur[d], 1);
}

__global__ void __launch_bounds__(256) k_scanA(int n) {
    __shared__ int sh[256];
    int b = blockIdx.x, t = threadIdx.x;
    int base = b * 1024 + t * 4;
    int4 v = make_int4(0, 0, 0, 0);
    if (base + 3 < n) v = *(const int4*)(g_cur + base);
    else {
        if (base     < n) v.x = g_cur[base];
        if (base + 1 < n) v.y = g_cur[base + 1];
        if (base + 2 < n) v.z = g_cur[base + 2];
    }
    int s = v.x + v.y + v.z + v.w;
    sh[t] = s;
    __syncthreads();
    for (int off = 1; off < 256; off <<= 1) {
        int u = (t >= off) ? sh[t - off] : 0;
        __syncthreads();
        sh[t] += u;
        __syncthreads();
    }
    int excl = sh[t] - s;
    if (t == 255) g_bsum[b] = sh[255];
    int4 o;
    o.x = excl; o.y = o.x + v.x; o.z = o.y + v.y; o.w = o.z + v.z;
    if (base + 3 < n) *(int4*)(g_off + base) = o;
    else {
        if (base     < n) g_off[base]     = o.x;
        if (base + 1 < n) g_off[base + 1] = o.y;
        if (base + 2 < n) g_off[base + 2] = o.z;
    }
}

__global__ void k_scanB(int nb) {
    __shared__ int sh[64];
    int t = threadIdx.x;
    int v = (t < nb) ? g_bsum[t] : 0;
    sh[t] = v;
    __syncthreads();
    for (int off = 1; off < 64; off <<= 1) {
        int u = (t >= off) ? sh[t - off] : 0;
        __syncthreads();
        sh[t] += u;
        __syncthreads();
    }
    if (t < nb) g_bpre[t] = sh[t] - v;
}

__global__ void k_scanC(int n, int etot) {
    int i = blockIdx.x * blockDim.x + threadIdx.x;
    if (i < n) {
        int v = g_off[i] + g_bpre[i >> 10];
        g_off[i] = v;
        g_cur[i] = v;
    }
    if (i == 0) g_off[n] = etot;
}

__global__ void k_scatter(const int* __restrict__ ei, int e, int etot) {
    int i = blockIdx.x * blockDim.x + threadIdx.x;
    if (i >= etot) return;
    int s, d;
    if (i < e) { s = ei[i]; d = ei[e + i]; } else { s = d = i - e; }
    int pos = atomicAdd(&g_cur[d], 1);
    g_csrc[pos] = s;
}

// -------------- GAT layer-1 aggregation (warp/dst, single pass) -----------------
// Lane l handles output columns 8l..8l+7 (head = l>>3). Per-head softmax uses the
// global bound M_h; every lane accumulates its head's full denominator.
__global__ void __launch_bounds__(256) k_agg1(const float* __restrict__ b1, int n) {
    int w = (blockIdx.x * blockDim.x + threadIdx.x) >> 5;
    int l = threadIdx.x & 31;
    if (w >= n) return;
    int head = l >> 3;
    float adh = g_ad1[4 * w + head];
    float Mh = lrelu(dec_max(g_emax[head]) + dec_max(g_emax[4 + head]));
    int start = g_off[w], end = g_off[w + 1];

    float acc[8];
#pragma unroll
    for (int q = 0; q < 8; q++) acc[q] = 0.f;
    float den = 0.f;
    const __half* xw = g_xw1h;

    int i = start;
    for (; i + 2 <= end; i += 2) {
        int s0 = g_csrc[i], s1 = g_csrc[i + 1];
        float e0 = g_as1[4 * s0 + head];
        float e1 = g_as1[4 * s1 + head];
        uint4 x0 = *(const uint4*)(xw + (size_t)s0 * F1 + 8 * l);
        uint4 x1 = *(const uint4*)(xw + (size_t)s1 * F1 + 8 * l);
        float w0 = __expf(lrelu(e0 + adh) - Mh);
        float w1 = __expf(lrelu(e1 + adh) - Mh);
        den += w0 + w1;
        float4 a0 = h4f(make_uint2(x0.x, x0.y)), a1 = h4f(make_uint2(x0.z, x0.w));
        float4 c0 = h4f(make_uint2(x1.x, x1.y)), c1 = h4f(make_uint2(x1.z, x1.w));
        acc[0] += a0.x * w0 + c0.x * w1;
        acc[1] += a0.y * w0 + c0.y * w1;
        acc[2] += a0.z * w0 + c0.z * w1;
        acc[3] += a0.w * w0 + c0.w * w1;
        acc[4] += a1.x * w0 + c1.x * w1;
        acc[5] += a1.y * w0 + c1.y * w1;
        acc[6] += a1.z * w0 + c1.z * w1;
        acc[7] += a1.w * w0 + c1.w * w1;
    }
    if (i < end) {
        int s0 = g_csrc[i];
        float e0 = g_as1[4 * s0 + head];
        uint4 x0 = *(const uint4*)(xw + (size_t)s0 * F1 + 8 * l);
        float w0 = __expf(lrelu(e0 + adh) - Mh);
        den += w0;
        float4 a0 = h4f(make_uint2(x0.x, x0.y)), a1 = h4f(make_uint2(x0.z, x0.w));
        acc[0] += a0.x * w0; acc[1] += a0.y * w0;
        acc[2] += a0.z * w0; acc[3] += a0.w * w0;
        acc[4] += a1.x * w0; acc[5] += a1.y * w0;
        acc[6] += a1.z * w0; acc[7] += a1.w * w0;
    }
    float r = 1.f / den;
    const float* bp = b1 + 8 * l;
    float4 bb0 = *(const float4*)bp;
    float4 bb1 = *(const float4*)(bp + 4);
    __half2 q0 = __floats2half2_rn(eluf(acc[0] * r + bb0.x), eluf(acc[1] * r + bb0.y));
    __half2 q1 = __floats2half2_rn(eluf(acc[2] * r + bb0.z), eluf(acc[3] * r + bb0.w));
    __half2 q2 = __floats2half2_rn(eluf(acc[4] * r + bb1.x), eluf(acc[5] * r + bb1.y));
    __half2 q3 = __floats2half2_rn(eluf(acc[6] * r + bb1.z), eluf(acc[7] * r + bb1.w));
    uint4 st;
    st.x = *(unsigned*)&q0; st.y = *(unsigned*)&q1;
    st.z = *(unsigned*)&q2; st.w = *(unsigned*)&q3;
    *(uint4*)(g_h2h + (size_t)w * F1 + 8 * l) = st;
}

// -------------- GAT layer-2 aggregation (warp/dst, single pass) -----------------
__global__ void __launch_bounds__(256) k_agg2(const float* __restrict__ b2, int n) {
    int w = (blockIdx.x * blockDim.x + threadIdx.x) >> 5;
    int l = threadIdx.x & 31;
    if (w >= n) return;
    int start = g_off[w], end = g_off[w + 1];
    float adv = g_ad2[w];
    float M2 = lrelu(dec_max(g_emax[8]) + dec_max(g_emax[9]));

    float2 acc = make_float2(0.f, 0.f);
    float den = 0.f;
    int i = start;
    for (; i + 2 <= end; i += 2) {
        int s0 = g_csrc[i], s1 = g_csrc[i + 1];
        float e0 = __expf(lrelu(g_as2[s0] + adv) - M2);
        float e1 = __expf(lrelu(g_as2[s1] + adv) - M2);
        float2 x0 = __half22float2(*(const __half2*)&g_xw2h[(size_t)s0 * HID + 2 * l]);
        float2 x1 = __half22float2(*(const __half2*)&g_xw2h[(size_t)s1 * HID + 2 * l]);
        den += e0 + e1;
        acc.x += x0.x * e0 + x1.x * e1;
        acc.y += x0.y * e0 + x1.y * e1;
    }
    if (i < end) {
        int s0 = g_csrc[i];
        float e0 = __expf(lrelu(g_as2[s0] + adv) - M2);
        float2 x0 = __half22float2(*(const __half2*)&g_xw2h[(size_t)s0 * HID + 2 * l]);
        den += e0;
        acc.x += x0.x * e0;
        acc.y += x0.y * e0;
    }
    float r = 1.f / den;
    float2 bb = ((const float2*)b2)[l];
    float2 o;
    o.x = eluf(acc.x * r + bb.x);
    o.y = eluf(acc.y * r + bb.y);
    *(float2*)(g_h3 + (size_t)w * HID + 2 * l) = o;
}

// ------------------------- logits + block max (warp per row) --------------------
__global__ void __launch_bounds__(256) k_logits(const float* __restrict__ Wout,
                                                const float* __restrict__ bout,
                                                float* __restrict__ out, int n)
{
    __shared__ float sm[8];
    int wi = threadIdx.x >> 5;
    int l = threadIdx.x & 31;
    int row = blockIdx.x * 8 + wi;
    float lg = -3.402823466e38f;
    if (row < n) {
        float2 hv = ((const float2*)(g_h3 + (size_t)row * HID))[l];
        float2 wv = ((const float2*)Wout)[l];
        float p = hv.x * wv.x + hv.y * wv.y;
#pragma unroll
        for (int off = 16; off; off >>= 1) p += __shfl_xor_sync(0xffffffffu, p, off);
        lg = p + bout[0];
        if (l == 0) out[n + row] = lg;
    }
    if (l == 0) sm[wi] = lg;
    __syncthreads();
    if (threadIdx.x == 0) {
        float mx = sm[0];
#pragma unroll
        for (int k = 1; k < 8; k++) mx = fmaxf(mx, sm[k]);
        atomicMax(&g_maxbits, encf(mx));
    }
}

__global__ void k_expsum(const float* __restrict__ out, int n) {
    __shared__ float sm[256];
    float M = dec_max(g_maxbits);
    float s = 0.f;
    for (int i = blockIdx.x * blockDim.x + threadIdx.x; i < n; i += gridDim.x * blockDim.x)
        s += __expf(out[n + i] - M);
    sm[threadIdx.x] = s;
    __syncthreads();
    for (int off = 128; off; off >>= 1) {
        if (threadIdx.x < off) sm[threadIdx.x] += sm[threadIdx.x + off];
        __syncthreads();
    }
    if (threadIdx.x == 0) atomicAdd(&g_sumexp, sm[0]);
}

__global__ void k_weights(float* __restrict__ out, int n) {
    int i = blockIdx.x * blockDim.x + threadIdx.x;
    if (i >= n) return;
    float M = dec_max(g_maxbits);
    float S = g_sumexp;
    out[i] = __expf(out[n + i] - M) / S;
}

// ------------------------- launch -------------------------
extern "C" void kernel_launch(void* const* d_in, const int* in_sizes, int n_in,
                              void* d_out, int out_size)
{
    const float* x    = (const float*)d_in[0];
    const int*   ei   = (const int*)d_in[1];
    const float* reg  = (const float*)d_in[2];
    const float* ng   = (const float*)d_in[3];
    const float* nb   = (const float*)d_in[4];
    const float* rg   = (const float*)d_in[5];
    const float* rb   = (const float*)d_in[6];
    const float* W1   = (const float*)d_in[7];
    const float* as1  = (const float*)d_in[8];
    const float* ad1  = (const float*)d_in[9];
    const float* b1   = (const float*)d_in[10];
    const float* W2   = (const float*)d_in[11];
    const float* as2  = (const float*)d_in[12];
    const float* ad2  = (const float*)d_in[13];
    const float* b2   = (const float*)d_in[14];
    const float* Wout = (const float*)d_in[15];
    const float* bout = (const float*)d_in[16];
    float* out = (float*)d_out;

    int n = in_sizes[0] / FIN;
    int e = in_sizes[1] / 2;
    int etot = e + n;
    int wb = (n + 7) / 8;
    int nbScan = (n + 1023) / 1024;

    k_init<<<(n + 255) / 256, 256>>>(n);
    k_rownorm<<<wb, 256>>>(x, ng, nb, n);
    k_prepW<<<(F1 * FIN + HID * F1 + 255) / 256, 256>>>(W1, W2);
    k_cvec<<<1, 256>>>(reg, rg, rb, W1);

    dim3 g1(2, (n + 127) / 128);
    k_hgemm<0, 128, 128, 64, 64, 32><<<g1, 256>>>(n, FIN);

    k_alpha1<<<wb, 256>>>(as1, ad1, n);

    k_count<<<(etot + 255) / 256, 256>>>(ei, e, etot);
    k_scanA<<<nbScan, 256>>>(n);
    k_scanB<<<1, 64>>>(nbScan);
    k_scanC<<<(n + 255) / 256, 256>>>(n, etot);
    k_scatter<<<(etot + 255) / 256, 256>>>(ei, e, etot);

    k_agg1<<<wb, 256>>>(b1, n);

    dim3 g2(1, (n + 127) / 128);
    k_hgemm<1, 128, 64, 64, 32, 32><<<g2, 256>>>(n, F1);

    k_alpha2<<<wb, 256>>>(as2, ad2, n);
    k_agg2<<<wb, 256>>>(b2, n);

    k_logits<<<wb, 256>>>(Wout, bout, out, n);
    k_expsum<<<256, 256>>>(out, n);
    k_weights<<<(n + 255) / 256, 256>>>(out, n);
}

// round 6
// speedup vs baseline: 1.9772x; 1.0526x over previous
#include <cuda_runtime.h>
#include <cuda_fp16.h>
#include <cstdint>

#define N_MAX 50000
#define E_MAX 1600000
#define ET_MAX (N_MAX + E_MAX)
#define FIN 128
#define F1 256
#define HID 64

#define NEG_SLOPE 0.2f
#define LN_EPS 1e-5f

// ------------------------- scratch (device globals; no allocation) ----------
__device__ __half g_xnh[(size_t)N_MAX * FIN];    // normalized node features (fp16)
__device__ __half g_w1t[(size_t)F1 * FIN];       // W1[0:128,:]^T  [256][128] fp16
__device__ __half g_w2t[(size_t)HID * F1];       // W2^T           [64][256]  fp16
__device__ __half g_xw1h[(size_t)N_MAX * F1];    // layer-1 projected (fp16)
__device__ float  g_as1[N_MAX * 4];
__device__ float  g_ad1[N_MAX * 4];
__device__ __half g_h2h[(size_t)N_MAX * F1];     // layer-1 output (ELU, fp16)
__device__ __half g_xw2h[(size_t)N_MAX * HID];   // layer-2 projected (fp16)
__device__ float  g_as2[N_MAX];
__device__ float  g_ad2[N_MAX];
__device__ float  g_h3[(size_t)N_MAX * HID];     // layer-2 output (ELU)
__device__ int    g_off[N_MAX + 1];              // CSR offsets (by dst)
__device__ int    g_cnt[N_MAX];                  // degree counts (zero-invariant across calls)
__device__ int    g_cur[N_MAX];                  // scatter cursors
__device__ int    g_csrc[ET_MAX];                // CSR src node ids
__device__ float  g_rn[16];                      // LN'd regime features
__device__ int    g_bsum[64];                    // scan block totals
__device__ unsigned g_emax[10];                  // encoded per-head alpha maxes
__device__ unsigned g_maxbits;                   // encoded global max (softmax)
__device__ float  g_sumexp;

static __device__ __forceinline__ float lrelu(float x) { return x > 0.f ? x : NEG_SLOPE * x; }
static __device__ __forceinline__ float eluf(float x)  { return x > 0.f ? x : (__expf(x) - 1.f); }
static __device__ __forceinline__ unsigned encf(float x) {
    unsigned u = __float_as_uint(x);
    return (u & 0x80000000u) ? ~u : (u | 0x80000000u);
}
static __device__ __forceinline__ float dec_max(unsigned u) {
    return (u & 0x80000000u) ? __uint_as_float(u & 0x7fffffffu) : __uint_as_float(~u);
}
static __device__ __forceinline__ float4 h4f(uint2 u) {
    __half2 a = *(__half2*)&u.x;
    __half2 b = *(__half2*)&u.y;
    float2 fa = __half22float2(a), fb = __half22float2(b);
    return make_float4(fa.x, fa.y, fb.x, fb.y);
}

static __device__ __forceinline__ void ldsm4(unsigned* r, const void* p) {
    unsigned addr = (unsigned)__cvta_generic_to_shared(p);
    asm volatile("ldmatrix.sync.aligned.m8n8.x4.shared.b16 {%0,%1,%2,%3}, [%4];\n"
                 : "=r"(r[0]), "=r"(r[1]), "=r"(r[2]), "=r"(r[3]) : "r"(addr));
}
static __device__ __forceinline__ void mma16816f(float* d, const unsigned* a, const unsigned* b) {
    asm volatile(
        "mma.sync.aligned.m16n8k16.row.col.f32.f16.f16.f32 "
        "{%0,%1,%2,%3}, {%4,%5,%6,%7}, {%8,%9}, {%0,%1,%2,%3};\n"
        : "+f"(d[0]), "+f"(d[1]), "+f"(d[2]), "+f"(d[3])
        : "r"(a[0]), "r"(a[1]), "r"(a[2]), "r"(a[3]), "r"(b[0]), "r"(b[1]));
}

// ===================== phase 1: rownorm || prepW || count || regime/zeros =====
// block layout: [0,wb) rownorm; [wb,wb+PWB) prepW; [wb+PWB, wb+PWB+cntB) count;
// last block: regime LN + scalar zeroing.
#define PWB 192   // (256*128 + 64*256) / 256

__global__ void __launch_bounds__(256) k_phase1(
    const float* __restrict__ x, const float* __restrict__ gamma,
    const float* __restrict__ beta,
    const float* __restrict__ reg, const float* __restrict__ rg,
    const float* __restrict__ rb,
    const float* __restrict__ W1, const float* __restrict__ W2,
    const int* __restrict__ ei,
    int n, int e, int etot, int wb, int cntB)
{
    int b = blockIdx.x;
    if (b < wb) {
        // ---- row layernorm -> fp16
        int wi = threadIdx.x >> 5;
        int l = threadIdx.x & 31;
        int w = b * 8 + wi;
        if (w >= n) return;
        float4 v = ((const float4*)(x + (size_t)w * FIN))[l];
        float s  = v.x + v.y + v.z + v.w;
        float ss = v.x*v.x + v.y*v.y + v.z*v.z + v.w*v.w;
#pragma unroll
        for (int off = 16; off; off >>= 1) {
            s  += __shfl_xor_sync(0xffffffffu, s, off);
            ss += __shfl_xor_sync(0xffffffffu, ss, off);
        }
        float mu = s * (1.f / FIN);
        float var = ss * (1.f / FIN) - mu * mu;
        float rstd = rsqrtf(var + LN_EPS);
        float4 g = ((const float4*)gamma)[l];
        float4 bb = ((const float4*)beta)[l];
        __half2 p0 = __floats2half2_rn((v.x - mu) * rstd * g.x + bb.x,
                                       (v.y - mu) * rstd * g.y + bb.y);
        __half2 p1 = __floats2half2_rn((v.z - mu) * rstd * g.z + bb.z,
                                       (v.w - mu) * rstd * g.w + bb.w);
        uint2 u; u.x = *(unsigned*)&p0; u.y = *(unsigned*)&p1;
        *(uint2*)(g_xnh + (size_t)w * FIN + 4 * l) = u;
    } else if (b < wb + PWB) {
        // ---- weight transposes to fp16
        int i = (b - wb) * 256 + threadIdx.x;
        if (i < F1 * FIN) {
            int nn = i >> 7, kk = i & 127;
            g_w1t[i] = __float2half(W1[(size_t)kk * F1 + nn]);
        } else {
            int j = i - F1 * FIN;
            if (j < HID * F1) {
                int nn = j >> 8, kk = j & 255;
                g_w2t[j] = __float2half(W2[(size_t)kk * HID + nn]);
            }
        }
    } else if (b < wb + PWB + cntB) {
        // ---- degree count (4 edges / thread)
        int base = (b - wb - PWB) * 1024 + threadIdx.x * 4;
        if (base + 3 < e) {
            int4 dd = *(const int4*)(ei + e + base);
            atomicAdd(&g_cnt[dd.x], 1);
            atomicAdd(&g_cnt[dd.y], 1);
            atomicAdd(&g_cnt[dd.z], 1);
            atomicAdd(&g_cnt[dd.w], 1);
        } else {
#pragma unroll
            for (int j = 0; j < 4; j++) {
                int i = base + j;
                if (i < etot) {
                    int d = (i < e) ? ei[e + i] : (i - e);
                    atomicAdd(&g_cnt[d], 1);
                }
            }
        }
    } else {
        // ---- regime LN + scalar zeroing
        int t = threadIdx.x;
        if (t < 32) {
            float v = (t < 16) ? reg[t] : 0.f;
            float s = v, ss = v * v;
#pragma unroll
            for (int off = 16; off; off >>= 1) {
                s  += __shfl_xor_sync(0xffffffffu, s, off);
                ss += __shfl_xor_sync(0xffffffffu, ss, off);
            }
            float mu = s * (1.f / 16.f);
            float var = ss * (1.f / 16.f) - mu * mu;
            float rstd = rsqrtf(var + LN_EPS);
            if (t < 16) g_rn[t] = (v - mu) * rstd * rg[t] + rb[t];
        }
        if (t >= 32 && t < 42) g_emax[t - 32] = 0u;
        if (t == 42) g_maxbits = 0u;
        if (t == 43) g_sumexp = 0.f;
    }
}

// ===================== phase 2: GEMM1 (tensor cores) || scanA =================
// GEMM blocks [0, nGB): xw1h = xnh @ w1t^T + cvec(from g_rn,W1).
// Blocks [nGB, nGB+nbScan): per-1024-chunk prefix scan of g_cnt -> g_off partial,
// re-zeroing g_cnt (preserves cross-call invariant), totals to g_bsum.
__global__ void __launch_bounds__(256) k_gemm1_scan(const float* __restrict__ W1,
                                                    int M, int nGB)
{
    constexpr int BM = 128, BN = 128, BK = 64, WM = 64, WN = 32;
    constexpr int LDSM = BK + 8;
    __shared__ __align__(16) __half As[BM][LDSM];
    __shared__ __align__(16) __half Bs[BN][LDSM];
    __shared__ float cvs[BN];
    __shared__ int ssc[256];

    int b = blockIdx.x;
    int tid = threadIdx.x;

    if (b >= nGB) {
        // ---- scanA chunk
        int sb = b - nGB;
        int n = M;
        int base = sb * 1024 + tid * 4;
        int4 v = make_int4(0, 0, 0, 0);
        if (base + 3 < n) {
            v = *(const int4*)(g_cnt + base);
            *(int4*)(g_cnt + base) = make_int4(0, 0, 0, 0);
        } else {
            if (base     < n) { v.x = g_cnt[base];     g_cnt[base] = 0; }
            if (base + 1 < n) { v.y = g_cnt[base + 1]; g_cnt[base + 1] = 0; }
            if (base + 2 < n) { v.z = g_cnt[base + 2]; g_cnt[base + 2] = 0; }
        }
        int s = v.x + v.y + v.z + v.w;
        ssc[tid] = s;
        __syncthreads();
        for (int off = 1; off < 256; off <<= 1) {
            int u = (tid >= off) ? ssc[tid - off] : 0;
            __syncthreads();
            ssc[tid] += u;
            __syncthreads();
        }
        int excl = ssc[tid] - s;
        if (tid == 255) g_bsum[sb] = ssc[255];
        int4 o;
        o.x = excl; o.y = o.x + v.x; o.z = o.y + v.y; o.w = o.z + v.z;
        if (base + 3 < n) *(int4*)(g_off + base) = o;
        else {
            if (base     < n) g_off[base]     = o.x;
            if (base + 1 < n) g_off[base + 1] = o.y;
            if (base + 2 < n) g_off[base + 2] = o.z;
        }
        return;
    }

    // ---- GEMM tile
    constexpr int K = FIN;
    int bx = b & 1, by = b >> 1;
    int wid = tid >> 5, lane = tid & 31;
    constexpr int NWN = BN / WN;
    int wm = wid / NWN, wn = wid % NWN;
    constexpr int MT = WM / 16, NT = WN / 8;
    int rb = by * BM, cb = bx * BN;
    int lr = lane & 7, grp = lane >> 3;

    // cvec for this block's columns (from LN'd regime)
    if (tid < BN) {
        float s = 0.f;
#pragma unroll
        for (int k = 0; k < 16; k++)
            s += g_rn[k] * W1[(size_t)(FIN + k) * F1 + cb + tid];
        cvs[tid] = s;
    }

    float acc[MT][NT][4];
#pragma unroll
    for (int mt = 0; mt < MT; mt++)
#pragma unroll
        for (int nt = 0; nt < NT; nt++)
#pragma unroll
            for (int q = 0; q < 4; q++) acc[mt][nt][q] = 0.f;

    for (int k0 = 0; k0 < K; k0 += BK) {
        constexpr int AV = BM * BK / 8;
#pragma unroll
        for (int s = tid; s < AV; s += 256) {
            int row = s / (BK / 8), seg = s % (BK / 8);
            uint4 v = make_uint4(0u, 0u, 0u, 0u);
            if (rb + row < M) v = *(const uint4*)(g_xnh + (size_t)(rb + row) * K + k0 + seg * 8);
            *(uint4*)&As[row][seg * 8] = v;
        }
        constexpr int BV = BN * BK / 8;
#pragma unroll
        for (int s = tid; s < BV; s += 256) {
            int row = s / (BK / 8), seg = s % (BK / 8);
            *(uint4*)&Bs[row][seg * 8] = *(const uint4*)(g_w1t + (size_t)(cb + row) * K + k0 + seg * 8);
        }
        __syncthreads();
#pragma unroll
        for (int kk = 0; kk < BK; kk += 16) {
            unsigned a[MT][4], bfr[NT][2];
#pragma unroll
            for (int mt = 0; mt < MT; mt++) {
                int r = wm * WM + mt * 16 + (grp & 1) * 8 + lr;
                int c = kk + (grp >> 1) * 8;
                ldsm4(a[mt], &As[r][c]);
            }
#pragma unroll
            for (int np = 0; np < NT; np += 2) {
                int r = wn * WN + np * 8 + (grp >> 1) * 8 + lr;
                int c = kk + (grp & 1) * 8;
                unsigned t[4];
                ldsm4(t, &Bs[r][c]);
                bfr[np][0] = t[0]; bfr[np][1] = t[1];
                bfr[np + 1][0] = t[2]; bfr[np + 1][1] = t[3];
            }
#pragma unroll
            for (int mt = 0; mt < MT; mt++)
#pragma unroll
                for (int nt = 0; nt < NT; nt++)
                    mma16816f(acc[mt][nt], a[mt], bfr[nt]);
        }
        __syncthreads();
    }

    int qr = lane >> 2, qc = (lane & 3) * 2;
#pragma unroll
    for (int mt = 0; mt < MT; mt++)
#pragma unroll
        for (int nt = 0; nt < NT; nt++) {
            int row = rb + wm * WM + mt * 16 + qr;
            int lcol = wn * WN + nt * 8 + qc;
            int col = cb + lcol;
            float2 cv = *(const float2*)&cvs[lcol];
            if (row < M)
                *(__half2*)&g_xw1h[(size_t)row * F1 + col] =
                    __floats2half2_rn(acc[mt][nt][0] + cv.x, acc[mt][nt][1] + cv.y);
            if (row + 8 < M)
                *(__half2*)&g_xw1h[(size_t)(row + 8) * F1 + col] =
                    __floats2half2_rn(acc[mt][nt][2] + cv.x, acc[mt][nt][3] + cv.y);
        }
}

// ===================== GEMM2 (tensor cores), standalone =======================
__global__ void __launch_bounds__(256) k_hgemm2(int M) {
    constexpr int BM = 128, BN = 64, BK = 64, WM = 32, WN = 32, K = F1;
    constexpr int LDSM = BK + 8;
    __shared__ __align__(16) __half As[BM][LDSM];
    __shared__ __align__(16) __half Bs[BN][LDSM];

    int tid = threadIdx.x;
    int wid = tid >> 5, lane = tid & 31;
    constexpr int NWN = BN / WN;
    int wm = wid / NWN, wn = wid % NWN;
    constexpr int MT = WM / 16, NT = WN / 8;
    int rb = blockIdx.y * BM, cb = 0;
    int lr = lane & 7, grp = lane >> 3;

    float acc[MT][NT][4];
#pragma unroll
    for (int mt = 0; mt < MT; mt++)
#pragma unroll
        for (int nt = 0; nt < NT; nt++)
#pragma unroll
            for (int q = 0; q < 4; q++) acc[mt][nt][q] = 0.f;

    for (int k0 = 0; k0 < K; k0 += BK) {
        constexpr int AV = BM * BK / 8;
#pragma unroll
        for (int s = tid; s < AV; s += 256) {
            int row = s / (BK / 8), seg = s % (BK / 8);
            uint4 v = make_uint4(0u, 0u, 0u, 0u);
            if (rb + row < M) v = *(const uint4*)(g_h2h + (size_t)(rb + row) * K + k0 + seg * 8);
            *(uint4*)&As[row][seg * 8] = v;
        }
        constexpr int BV = BN * BK / 8;
#pragma unroll
        for (int s = tid; s < BV; s += 256) {
            int row = s / (BK / 8), seg = s % (BK / 8);
            *(uint4*)&Bs[row][seg * 8] = *(const uint4*)(g_w2t + (size_t)(cb + row) * K + k0 + seg * 8);
        }
        __syncthreads();
#pragma unroll
        for (int kk = 0; kk < BK; kk += 16) {
            unsigned a[MT][4], bfr[NT][2];
#pragma unroll
            for (int mt = 0; mt < MT; mt++) {
                int r = wm * WM + mt * 16 + (grp & 1) * 8 + lr;
                int c = kk + (grp >> 1) * 8;
                ldsm4(a[mt], &As[r][c]);
            }
#pragma unroll
            for (int np = 0; np < NT; np += 2) {
                int r = wn * WN + np * 8 + (grp >> 1) * 8 + lr;
                int c = kk + (grp & 1) * 8;
                unsigned t[4];
                ldsm4(t, &Bs[r][c]);
                bfr[np][0] = t[0]; bfr[np][1] = t[1];
                bfr[np + 1][0] = t[2]; bfr[np + 1][1] = t[3];
            }
#pragma unroll
            for (int mt = 0; mt < MT; mt++)
#pragma unroll
                for (int nt = 0; nt < NT; nt++)
                    mma16816f(acc[mt][nt], a[mt], bfr[nt]);
        }
        __syncthreads();
    }

    int qr = lane >> 2, qc = (lane & 3) * 2;
#pragma unroll
    for (int mt = 0; mt < MT; mt++)
#pragma unroll
        for (int nt = 0; nt < NT; nt++) {
            int row = rb + wm * WM + mt * 16 + qr;
            int col = cb + wn * WN + nt * 8 + qc;
            if (row < M)
                *(__half2*)&g_xw2h[(size_t)row * HID + col] =
                    __floats2half2_rn(acc[mt][nt][0], acc[mt][nt][1]);
            if (row + 8 < M)
                *(__half2*)&g_xw2h[(size_t)(row + 8) * HID + col] =
                    __floats2half2_rn(acc[mt][nt][2], acc[mt][nt][3]);
        }
}

// ============ alpha1 + per-head maxes || scanC (inline block prefixes) ========
__global__ void __launch_bounds__(256) k_alpha1_fin(const float* __restrict__ asrc,
                                                    const float* __restrict__ adst,
                                                    int n, int wb, int etot)
{
    int b = blockIdx.x;
    if (b < wb) {
        __shared__ float smax[8][8];
        int wi = threadIdx.x >> 5;
        int l = threadIdx.x & 31;
        int w = b * 8 + wi;
        const float NEGINF = -3.402823466e38f;
        float ps1 = NEGINF, ps2 = NEGINF, pd1 = NEGINF, pd2 = NEGINF;

        if (w < n) {
            const uint2* xr = (const uint2*)(g_xw1h + (size_t)w * F1);
            float4 x1 = h4f(xr[l]), x2 = h4f(xr[32 + l]);
            float4 s1 = ((const float4*)asrc)[l], s2 = ((const float4*)asrc)[32 + l];
            float4 d1 = ((const float4*)adst)[l], d2 = ((const float4*)adst)[32 + l];
            ps1 = x1.x*s1.x + x1.y*s1.y + x1.z*s1.z + x1.w*s1.w;
            ps2 = x2.x*s2.x + x2.y*s2.y + x2.z*s2.z + x2.w*s2.w;
            pd1 = x1.x*d1.x + x1.y*d1.y + x1.z*d1.z + x1.w*d1.w;
            pd2 = x2.x*d2.x + x2.y*d2.y + x2.z*d2.z + x2.w*d2.w;
#pragma unroll
            for (int off = 8; off; off >>= 1) {
                ps1 += __shfl_xor_sync(0xffffffffu, ps1, off);
                ps2 += __shfl_xor_sync(0xffffffffu, ps2, off);
                pd1 += __shfl_xor_sync(0xffffffffu, pd1, off);
                pd2 += __shfl_xor_sync(0xffffffffu, pd2, off);
            }
            if (l == 0)  { g_as1[w*4+0] = ps1; g_as1[w*4+2] = ps2; g_ad1[w*4+0] = pd1; g_ad1[w*4+2] = pd2; }
            if (l == 16) { g_as1[w*4+1] = ps1; g_as1[w*4+3] = ps2; g_ad1[w*4+1] = pd1; g_ad1[w*4+3] = pd2; }
        }
        if (l == 0)  { smax[0][wi] = ps1; smax[2][wi] = ps2; smax[4][wi] = pd1; smax[6][wi] = pd2; }
        if (l == 16) { smax[1][wi] = ps1; smax[3][wi] = ps2; smax[5][wi] = pd1; smax[7][wi] = pd2; }
        __syncthreads();
        if (threadIdx.x < 8) {
            float m = smax[threadIdx.x][0];
#pragma unroll
            for (int k = 1; k < 8; k++) m = fmaxf(m, smax[threadIdx.x][k]);
            if (m > -3.3e38f) atomicMax(&g_emax[threadIdx.x], encf(m));
        }
    } else {
        // ---- scanC chunk: add block prefix (computed inline from g_bsum)
        __shared__ int sbp;
        int cb2 = b - wb;
        int lane = threadIdx.x & 31;
        if (threadIdx.x < 32) {
            int s = 0;
            for (int j = lane; j < cb2; j += 32) s += g_bsum[j];
#pragma unroll
            for (int off = 16; off; off >>= 1) s += __shfl_xor_sync(0xffffffffu, s, off);
            if (lane == 0) sbp = s;
        }
        __syncthreads();
        int bpre = sbp;
        int base = cb2 * 1024 + threadIdx.x * 4;
        if (base + 3 < n) {
            int4 v = *(const int4*)(g_off + base);
            v.x += bpre; v.y += bpre; v.z += bpre; v.w += bpre;
            *(int4*)(g_off + base) = v;
            *(int4*)(g_cur + base) = v;
        } else {
#pragma unroll
            for (int j = 0; j < 4; j++) {
                int i = base + j;
                if (i < n) { int v = g_off[i] + bpre; g_off[i] = v; g_cur[i] = v; }
            }
        }
        if (cb2 == 0 && threadIdx.x == 0) g_off[n] = etot;
    }
}

// ------------------- alpha dots, layer 2 + global maxes -------------------------
__global__ void __launch_bounds__(256) k_alpha2(const float* __restrict__ asrc,
                                                const float* __restrict__ adst, int n)
{
    __shared__ float smax[2][8];
    int wi = threadIdx.x >> 5;
    int l = threadIdx.x & 31;
    int w = blockIdx.x * 8 + wi;
    const float NEGINF = -3.402823466e38f;
    float p = NEGINF, q = NEGINF;
    if (w < n) {
        __half2 hx = *(const __half2*)&g_xw2h[(size_t)w * HID + 2 * l];
        float2 xf = __half22float2(hx);
        float2 sv = ((const float2*)asrc)[l];
        float2 dv = ((const float2*)adst)[l];
        p = xf.x * sv.x + xf.y * sv.y;
        q = xf.x * dv.x + xf.y * dv.y;
#pragma unroll
        for (int off = 16; off; off >>= 1) {
            p += __shfl_xor_sync(0xffffffffu, p, off);
            q += __shfl_xor_sync(0xffffffffu, q, off);
        }
        if (l == 0) { g_as2[w] = p; g_ad2[w] = q; }
    }
    if (l == 0) { smax[0][wi] = p; smax[1][wi] = q; }
    __syncthreads();
    if (threadIdx.x < 2) {
        float m = smax[threadIdx.x][0];
#pragma unroll
        for (int k = 1; k < 8; k++) m = fmaxf(m, smax[threadIdx.x][k]);
        if (m > NEGINF) atomicMax(&g_emax[8 + threadIdx.x], encf(m));
    }
}

// ------------------------- scatter -------------------------
__global__ void k_scatter(const int* __restrict__ ei, int e, int etot) {
    int i = blockIdx.x * blockDim.x + threadIdx.x;
    if (i >= etot) return;
    int s, d;
    if (i < e) { s = ei[i]; d = ei[e + i]; } else { s = d = i - e; }
    int pos = atomicAdd(&g_cur[d], 1);
    g_csrc[pos] = s;
}

// -------------- GAT layer-1 aggregation (warp/dst, single pass) -----------------
__global__ void __launch_bounds__(256) k_agg1(const float* __restrict__ b1, int n) {
    int w = (blockIdx.x * blockDim.x + threadIdx.x) >> 5;
    int l = threadIdx.x & 31;
    if (w >= n) return;
    int head = l >> 3;
    float adh = g_ad1[4 * w + head];
    float Mh = lrelu(dec_max(g_emax[head]) + dec_max(g_emax[4 + head]));
    int start = g_off[w], end = g_off[w + 1];

    float acc[8];
#pragma unroll
    for (int q = 0; q < 8; q++) acc[q] = 0.f;
    float den = 0.f;
    const __half* xw = g_xw1h;

    int i = start;
    for (; i + 2 <= end; i += 2) {
        int s0 = g_csrc[i], s1 = g_csrc[i + 1];
        float e0 = g_as1[4 * s0 + head];
        float e1 = g_as1[4 * s1 + head];
        uint4 x0 = *(const uint4*)(xw + (size_t)s0 * F1 + 8 * l);
        uint4 x1 = *(const uint4*)(xw + (size_t)s1 * F1 + 8 * l);
        float w0 = __expf(lrelu(e0 + adh) - Mh);
        float w1 = __expf(lrelu(e1 + adh) - Mh);
        den += w0 + w1;
        float4 a0 = h4f(make_uint2(x0.x, x0.y)), a1 = h4f(make_uint2(x0.z, x0.w));
        float4 c0 = h4f(make_uint2(x1.x, x1.y)), c1 = h4f(make_uint2(x1.z, x1.w));
        acc[0] += a0.x * w0 + c0.x * w1;
        acc[1] += a0.y * w0 + c0.y * w1;
        acc[2] += a0.z * w0 + c0.z * w1;
        acc[3] += a0.w * w0 + c0.w * w1;
        acc[4] += a1.x * w0 + c1.x * w1;
        acc[5] += a1.y * w0 + c1.y * w1;
        acc[6] += a1.z * w0 + c1.z * w1;
        acc[7] += a1.w * w0 + c1.w * w1;
    }
    if (i < end) {
        int s0 = g_csrc[i];
        float e0 = g_as1[4 * s0 + head];
        uint4 x0 = *(const uint4*)(xw + (size_t)s0 * F1 + 8 * l);
        float w0 = __expf(lrelu(e0 + adh) - Mh);
        den += w0;
        float4 a0 = h4f(make_uint2(x0.x, x0.y)), a1 = h4f(make_uint2(x0.z, x0.w));
        acc[0] += a0.x * w0; acc[1] += a0.y * w0;
        acc[2] += a0.z * w0; acc[3] += a0.w * w0;
        acc[4] += a1.x * w0; acc[5] += a1.y * w0;
        acc[6] += a1.z * w0; acc[7] += a1.w * w0;
    }
    float r = 1.f / den;
    const float* bp = b1 + 8 * l;
    float4 bb0 = *(const float4*)bp;
    float4 bb1 = *(const float4*)(bp + 4);
    __half2 q0 = __floats2half2_rn(eluf(acc[0] * r + bb0.x), eluf(acc[1] * r + bb0.y));
    __half2 q1 = __floats2half2_rn(eluf(acc[2] * r + bb0.z), eluf(acc[3] * r + bb0.w));
    __half2 q2 = __floats2half2_rn(eluf(acc[4] * r + bb1.x), eluf(acc[5] * r + bb1.y));
    __half2 q3 = __floats2half2_rn(eluf(acc[6] * r + bb1.z), eluf(acc[7] * r + bb1.w));
    uint4 st;
    st.x = *(unsigned*)&q0; st.y = *(unsigned*)&q1;
    st.z = *(unsigned*)&q2; st.w = *(unsigned*)&q3;
    *(uint4*)(g_h2h + (size_t)w * F1 + 8 * l) = st;
}

// -------------- GAT layer-2 aggregation (warp/dst, single pass) -----------------
__global__ void __launch_bounds__(256) k_agg2(const float* __restrict__ b2, int n) {
    int w = (blockIdx.x * blockDim.x + threadIdx.x) >> 5;
    int l = threadIdx.x & 31;
    if (w >= n) return;
    int start = g_off[w], end = g_off[w + 1];
    float adv = g_ad2[w];
    float M2 = lrelu(dec_max(g_emax[8]) + dec_max(g_emax[9]));

    float2 acc = make_float2(0.f, 0.f);
    float den = 0.f;
    int i = start;
    for (; i + 2 <= end; i += 2) {
        int s0 = g_csrc[i], s1 = g_csrc[i + 1];
        float e0 = __expf(lrelu(g_as2[s0] + adv) - M2);
        float e1 = __expf(lrelu(g_as2[s1] + adv) - M2);
        float2 x0 = __half22float2(*(const __half2*)&g_xw2h[(size_t)s0 * HID + 2 * l]);
        float2 x1 = __half22float2(*(const __half2*)&g_xw2h[(size_t)s1 * HID + 2 * l]);
        den += e0 + e1;
        acc.x += x0.x * e0 + x1.x * e1;
        acc.y += x0.y * e0 + x1.y * e1;
    }
    if (i < end) {
        int s0 = g_csrc[i];
        float e0 = __expf(lrelu(g_as2[s0] + adv) - M2);
        float2 x0 = __half22float2(*(const __half2*)&g_xw2h[(size_t)s0 * HID + 2 * l]);
        den += e0;
        acc.x += x0.x * e0;
        acc.y += x0.y * e0;
    }
    float r = 1.f / den;
    float2 bb = ((const float2*)b2)[l];
    float2 o;
    o.x = eluf(acc.x * r + bb.x);
    o.y = eluf(acc.y * r + bb.y);
    *(float2*)(g_h3 + (size_t)w * HID + 2 * l) = o;
}

// ------------------------- logits + block max (warp per row) --------------------
__global__ void __launch_bounds__(256) k_logits(const float* __restrict__ Wout,
                                                const float* __restrict__ bout,
                                                float* __restrict__ out, int n)
{
    __shared__ float sm[8];
    int wi = threadIdx.x >> 5;
    int l = threadIdx.x & 31;
    int row = blockIdx.x * 8 + wi;
    float lg = -3.402823466e38f;
    if (row < n) {
        float2 hv = ((const float2*)(g_h3 + (size_t)row * HID))[l];
        float2 wv = ((const float2*)Wout)[l];
        float p = hv.x * wv.x + hv.y * wv.y;
#pragma unroll
        for (int off = 16; off; off >>= 1) p += __shfl_xor_sync(0xffffffffu, p, off);
        lg = p + bout[0];
        if (l == 0) out[n + row] = lg;
    }
    if (l == 0) sm[wi] = lg;
    __syncthreads();
    if (threadIdx.x == 0) {
        float mx = sm[0];
#pragma unroll
        for (int k = 1; k < 8; k++) mx = fmaxf(mx, sm[k]);
        atomicMax(&g_maxbits, encf(mx));
    }
}

__global__ void k_expsum(const float* __restrict__ out, int n) {
    __shared__ float sm[256];
    float M = dec_max(g_maxbits);
    float s = 0.f;
    for (int i = blockIdx.x * blockDim.x + threadIdx.x; i < n; i += gridDim.x * blockDim.x)
        s += __expf(out[n + i] - M);
    sm[threadIdx.x] = s;
    __syncthreads();
    for (int off = 128; off; off >>= 1) {
        if (threadIdx.x < off) sm[threadIdx.x] += sm[threadIdx.x + off];
        __syncthreads();
    }
    if (threadIdx.x == 0) atomicAdd(&g_sumexp, sm[0]);
}

__global__ void k_weights(float* __restrict__ out, int n) {
    int i = blockIdx.x * blockDim.x + threadIdx.x;
    if (i >= n) return;
    float M = dec_max(g_maxbits);
    float S = g_sumexp;
    out[i] = __expf(out[n + i] - M) / S;
}

// ------------------------- launch -------------------------
extern "C" void kernel_launch(void* const* d_in, const int* in_sizes, int n_in,
                              void* d_out, int out_size)
{
    const float* x    = (const float*)d_in[0];
    const int*   ei   = (const int*)d_in[1];
    const float* reg  = (const float*)d_in[2];
    const float* ng   = (const float*)d_in[3];
    const float* nb   = (const float*)d_in[4];
    const float* rg   = (const float*)d_in[5];
    const float* rb   = (const float*)d_in[6];
    const float* W1   = (const float*)d_in[7];
    const float* as1  = (const float*)d_in[8];
    const float* ad1  = (const float*)d_in[9];
    const float* b1   = (const float*)d_in[10];
    const float* W2   = (const float*)d_in[11];
    const float* as2  = (const float*)d_in[12];
    const float* ad2  = (const float*)d_in[13];
    const float* b2   = (const float*)d_in[14];
    const float* Wout = (const float*)d_in[15];
    const float* bout = (const float*)d_in[16];
    float* out = (float*)d_out;

    int n = in_sizes[0] / FIN;
    int e = in_sizes[1] / 2;
    int etot = e + n;
    int wb = (n + 7) / 8;
    int nbScan = (n + 1023) / 1024;
    int cntB = (etot + 1023) / 1024;

    // phase 1: rownorm || prepW || count || regime-LN + zeros
    k_phase1<<<wb + PWB + cntB + 1, 256>>>(x, ng, nb, reg, rg, rb, W1, W2, ei,
                                           n, e, etot, wb, cntB);

    // phase 2: GEMM1 || scanA
    int nGB = 2 * ((n + 127) / 128);
    k_gemm1_scan<<<nGB + nbScan, 256>>>(W1, n, nGB);

    // alpha1 || scanC
    k_alpha1_fin<<<wb + nbScan, 256>>>(as1, ad1, n, wb, etot);

    k_scatter<<<(etot + 255) / 256, 256>>>(ei, e, etot);

    k_agg1<<<wb, 256>>>(b1, n);

    dim3 g2(1, (n + 127) / 128);
    k_hgemm2<<<g2, 256>>>(n);

    k_alpha2<<<wb, 256>>>(as2, ad2, n);
    k_agg2<<<wb, 256>>>(b2, n);

    k_logits<<<wb, 256>>>(Wout, bout, out, n);
    k_expsum<<<256, 256>>>(out, n);
    k_weights<<<(n + 255) / 256, 256>>>(out, n);
}

// round 7
// speedup vs baseline: 2.0744x; 1.0492x over previous
#include <cuda_runtime.h>
#include <cuda_fp16.h>
#include <cstdint>

#define N_MAX 50000
#define E_MAX 1600000
#define ET_MAX (N_MAX + E_MAX)
#define FIN 128
#define F1 256
#define HID 64

#define NEG_SLOPE 0.2f
#define LN_EPS 1e-5f

// ------------------------- scratch (device globals; no allocation) ----------
__device__ __half g_xnh[(size_t)N_MAX * FIN];    // normalized node features (fp16)
__device__ __half g_w1t[(size_t)F1 * FIN];       // W1[0:128,:]^T  [256][128] fp16
__device__ __half g_w2t[(size_t)HID * F1];       // W2^T           [64][256]  fp16
__device__ __half g_xw1h[(size_t)N_MAX * F1];    // layer-1 projected (fp16)
__device__ float  g_as1[N_MAX * 4];
__device__ float  g_ad1[N_MAX * 4];
__device__ __half g_h2h[(size_t)N_MAX * F1];     // layer-1 output (ELU, fp16)
__device__ __half g_xw2h[(size_t)N_MAX * HID];   // layer-2 projected (fp16)
__device__ float  g_as2[N_MAX];
__device__ float  g_ad2[N_MAX];
__device__ int    g_off[N_MAX + 1];              // CSR offsets (by dst)
__device__ int    g_cnt[N_MAX];                  // degree counts (zero-invariant across calls)
__device__ int    g_cur[N_MAX];                  // scatter cursors
__device__ int    g_csrc[ET_MAX];                // CSR src node ids
__device__ float  g_rn[16];                      // LN'd regime features
__device__ int    g_bsum[64];                    // scan block totals
__device__ unsigned g_emax[10];                  // encoded per-head alpha maxes
__device__ unsigned g_maxbits;                   // encoded global max (softmax)
__device__ float  g_sumexp;

static __device__ __forceinline__ float lrelu(float x) { return x > 0.f ? x : NEG_SLOPE * x; }
static __device__ __forceinline__ float eluf(float x)  { return x > 0.f ? x : (__expf(x) - 1.f); }
static __device__ __forceinline__ unsigned encf(float x) {
    unsigned u = __float_as_uint(x);
    return (u & 0x80000000u) ? ~u : (u | 0x80000000u);
}
static __device__ __forceinline__ float dec_max(unsigned u) {
    return (u & 0x80000000u) ? __uint_as_float(u & 0x7fffffffu) : __uint_as_float(~u);
}
static __device__ __forceinline__ float4 h4f(uint2 u) {
    __half2 a = *(__half2*)&u.x;
    __half2 b = *(__half2*)&u.y;
    float2 fa = __half22float2(a), fb = __half22float2(b);
    return make_float4(fa.x, fa.y, fb.x, fb.y);
}

static __device__ __forceinline__ void ldsm4(unsigned* r, const void* p) {
    unsigned addr = (unsigned)__cvta_generic_to_shared(p);
    asm volatile("ldmatrix.sync.aligned.m8n8.x4.shared.b16 {%0,%1,%2,%3}, [%4];\n"
                 : "=r"(r[0]), "=r"(r[1]), "=r"(r[2]), "=r"(r[3]) : "r"(addr));
}
static __device__ __forceinline__ void mma16816f(float* d, const unsigned* a, const unsigned* b) {
    asm volatile(
        "mma.sync.aligned.m16n8k16.row.col.f32.f16.f16.f32 "
        "{%0,%1,%2,%3}, {%4,%5,%6,%7}, {%8,%9}, {%0,%1,%2,%3};\n"
        : "+f"(d[0]), "+f"(d[1]), "+f"(d[2]), "+f"(d[3])
        : "r"(a[0]), "r"(a[1]), "r"(a[2]), "r"(a[3]), "r"(b[0]), "r"(b[1]));
}

// ===================== phase 1: rownorm || prepW || count || regime/zeros =====
#define PWB 192   // (256*128 + 64*256) / 256

__global__ void __launch_bounds__(256) k_phase1(
    const float* __restrict__ x, const float* __restrict__ gamma,
    const float* __restrict__ beta,
    const float* __restrict__ reg, const float* __restrict__ rg,
    const float* __restrict__ rb,
    const float* __restrict__ W1, const float* __restrict__ W2,
    const int* __restrict__ ei,
    int n, int e, int etot, int wb, int cntB)
{
    int b = blockIdx.x;
    if (b < wb) {
        int wi = threadIdx.x >> 5;
        int l = threadIdx.x & 31;
        int w = b * 8 + wi;
        if (w >= n) return;
        float4 v = ((const float4*)(x + (size_t)w * FIN))[l];
        float s  = v.x + v.y + v.z + v.w;
        float ss = v.x*v.x + v.y*v.y + v.z*v.z + v.w*v.w;
#pragma unroll
        for (int off = 16; off; off >>= 1) {
            s  += __shfl_xor_sync(0xffffffffu, s, off);
            ss += __shfl_xor_sync(0xffffffffu, ss, off);
        }
        float mu = s * (1.f / FIN);
        float var = ss * (1.f / FIN) - mu * mu;
        float rstd = rsqrtf(var + LN_EPS);
        float4 g = ((const float4*)gamma)[l];
        float4 bb = ((const float4*)beta)[l];
        __half2 p0 = __floats2half2_rn((v.x - mu) * rstd * g.x + bb.x,
                                       (v.y - mu) * rstd * g.y + bb.y);
        __half2 p1 = __floats2half2_rn((v.z - mu) * rstd * g.z + bb.z,
                                       (v.w - mu) * rstd * g.w + bb.w);
        uint2 u; u.x = *(unsigned*)&p0; u.y = *(unsigned*)&p1;
        *(uint2*)(g_xnh + (size_t)w * FIN + 4 * l) = u;
    } else if (b < wb + PWB) {
        int i = (b - wb) * 256 + threadIdx.x;
        if (i < F1 * FIN) {
            int nn = i >> 7, kk = i & 127;
            g_w1t[i] = __float2half(W1[(size_t)kk * F1 + nn]);
        } else {
            int j = i - F1 * FIN;
            if (j < HID * F1) {
                int nn = j >> 8, kk = j & 255;
                g_w2t[j] = __float2half(W2[(size_t)kk * HID + nn]);
            }
        }
    } else if (b < wb + PWB + cntB) {
        int base = (b - wb - PWB) * 1024 + threadIdx.x * 4;
        if (base + 3 < e) {
            int4 dd = *(const int4*)(ei + e + base);
            atomicAdd(&g_cnt[dd.x], 1);
            atomicAdd(&g_cnt[dd.y], 1);
            atomicAdd(&g_cnt[dd.z], 1);
            atomicAdd(&g_cnt[dd.w], 1);
        } else {
#pragma unroll
            for (int j = 0; j < 4; j++) {
                int i = base + j;
                if (i < etot) {
                    int d = (i < e) ? ei[e + i] : (i - e);
                    atomicAdd(&g_cnt[d], 1);
                }
            }
        }
    } else {
        int t = threadIdx.x;
        if (t < 32) {
            float v = (t < 16) ? reg[t] : 0.f;
            float s = v, ss = v * v;
#pragma unroll
            for (int off = 16; off; off >>= 1) {
                s  += __shfl_xor_sync(0xffffffffu, s, off);
                ss += __shfl_xor_sync(0xffffffffu, ss, off);
            }
            float mu = s * (1.f / 16.f);
            float var = ss * (1.f / 16.f) - mu * mu;
            float rstd = rsqrtf(var + LN_EPS);
            if (t < 16) g_rn[t] = (v - mu) * rstd * rg[t] + rb[t];
        }
        if (t >= 32 && t < 42) g_emax[t - 32] = 0u;
        if (t == 42) g_maxbits = 0u;
        if (t == 43) g_sumexp = 0.f;
    }
}

// ===================== scanA: per-1024-chunk prefix of g_cnt (re-zeroes it) ===
__global__ void __launch_bounds__(256) k_scanA(int n) {
    __shared__ int ssc[256];
    int sb = blockIdx.x, tid = threadIdx.x;
    int base = sb * 1024 + tid * 4;
    int4 v = make_int4(0, 0, 0, 0);
    if (base + 3 < n) {
        v = *(const int4*)(g_cnt + base);
        *(int4*)(g_cnt + base) = make_int4(0, 0, 0, 0);
    } else {
        if (base     < n) { v.x = g_cnt[base];     g_cnt[base] = 0; }
        if (base + 1 < n) { v.y = g_cnt[base + 1]; g_cnt[base + 1] = 0; }
        if (base + 2 < n) { v.z = g_cnt[base + 2]; g_cnt[base + 2] = 0; }
    }
    int s = v.x + v.y + v.z + v.w;
    ssc[tid] = s;
    __syncthreads();
    for (int off = 1; off < 256; off <<= 1) {
        int u = (tid >= off) ? ssc[tid - off] : 0;
        __syncthreads();
        ssc[tid] += u;
        __syncthreads();
    }
    int excl = ssc[tid] - s;
    if (tid == 255) g_bsum[sb] = ssc[255];
    int4 o;
    o.x = excl; o.y = o.x + v.x; o.z = o.y + v.y; o.w = o.z + v.z;
    if (base + 3 < n) *(int4*)(g_off + base) = o;
    else {
        if (base     < n) g_off[base]     = o.x;
        if (base + 1 < n) g_off[base + 1] = o.y;
        if (base + 2 < n) g_off[base + 2] = o.z;
    }
}

// ===================== scanC: add inline block prefixes, init cursors =========
__global__ void __launch_bounds__(256) k_scanC(int n, int etot) {
    __shared__ int sbp;
    int cb2 = blockIdx.x;
    int lane = threadIdx.x & 31;
    if (threadIdx.x < 32) {
        int s = 0;
        for (int j = lane; j < cb2; j += 32) s += g_bsum[j];
#pragma unroll
        for (int off = 16; off; off >>= 1) s += __shfl_xor_sync(0xffffffffu, s, off);
        if (lane == 0) sbp = s;
    }
    __syncthreads();
    int bpre = sbp;
    int base = cb2 * 1024 + threadIdx.x * 4;
    if (base + 3 < n) {
        int4 v = *(const int4*)(g_off + base);
        v.x += bpre; v.y += bpre; v.z += bpre; v.w += bpre;
        *(int4*)(g_off + base) = v;
        *(int4*)(g_cur + base) = v;
    } else {
#pragma unroll
        for (int j = 0; j < 4; j++) {
            int i = base + j;
            if (i < n) { int v = g_off[i] + bpre; g_off[i] = v; g_cur[i] = v; }
        }
    }
    if (cb2 == 0 && threadIdx.x == 0) g_off[n] = etot;
}

// ===================== phase 2: GEMM1 (tensor cores) || scatter ===============
__global__ void __launch_bounds__(256) k_phase2(const float* __restrict__ W1,
                                                const int* __restrict__ ei,
                                                int M, int e, int etot, int nGB)
{
    constexpr int BM = 128, BN = 128, BK = 64, WM = 64, WN = 32;
    constexpr int LDSM = BK + 8;
    __shared__ __align__(16) __half As[BM][LDSM];
    __shared__ __align__(16) __half Bs[BN][LDSM];
    __shared__ float cvs[BN];

    int b = blockIdx.x;
    int tid = threadIdx.x;

    if (b >= nGB) {
        // ---- scatter chunk: 1024 edges / block
        int base = (b - nGB) * 1024 + tid * 4;
        if (base + 3 < e) {
            int4 ssv = *(const int4*)(ei + base);
            int4 ddv = *(const int4*)(ei + e + base);
            g_csrc[atomicAdd(&g_cur[ddv.x], 1)] = ssv.x;
            g_csrc[atomicAdd(&g_cur[ddv.y], 1)] = ssv.y;
            g_csrc[atomicAdd(&g_cur[ddv.z], 1)] = ssv.z;
            g_csrc[atomicAdd(&g_cur[ddv.w], 1)] = ssv.w;
        } else {
#pragma unroll
            for (int j = 0; j < 4; j++) {
                int i = base + j;
                if (i < etot) {
                    int s, d;
                    if (i < e) { s = ei[i]; d = ei[e + i]; } else { s = d = i - e; }
                    g_csrc[atomicAdd(&g_cur[d], 1)] = s;
                }
            }
        }
        return;
    }

    // ---- GEMM1 tile
    constexpr int K = FIN;
    int bx = b & 1, by = b >> 1;
    int wid = tid >> 5, lane = tid & 31;
    constexpr int NWN = BN / WN;
    int wm = wid / NWN, wn = wid % NWN;
    constexpr int MT = WM / 16, NT = WN / 8;
    int rb = by * BM, cb = bx * BN;
    int lr = lane & 7, grp = lane >> 3;

    if (tid < BN) {
        float s = 0.f;
#pragma unroll
        for (int k = 0; k < 16; k++)
            s += g_rn[k] * W1[(size_t)(FIN + k) * F1 + cb + tid];
        cvs[tid] = s;
    }

    float acc[MT][NT][4];
#pragma unroll
    for (int mt = 0; mt < MT; mt++)
#pragma unroll
        for (int nt = 0; nt < NT; nt++)
#pragma unroll
            for (int q = 0; q < 4; q++) acc[mt][nt][q] = 0.f;

    for (int k0 = 0; k0 < K; k0 += BK) {
        constexpr int AV = BM * BK / 8;
#pragma unroll
        for (int s = tid; s < AV; s += 256) {
            int row = s / (BK / 8), seg = s % (BK / 8);
            uint4 v = make_uint4(0u, 0u, 0u, 0u);
            if (rb + row < M) v = *(const uint4*)(g_xnh + (size_t)(rb + row) * K + k0 + seg * 8);
            *(uint4*)&As[row][seg * 8] = v;
        }
        constexpr int BV = BN * BK / 8;
#pragma unroll
        for (int s = tid; s < BV; s += 256) {
            int row = s / (BK / 8), seg = s % (BK / 8);
            *(uint4*)&Bs[row][seg * 8] = *(const uint4*)(g_w1t + (size_t)(cb + row) * K + k0 + seg * 8);
        }
        __syncthreads();
#pragma unroll
        for (int kk = 0; kk < BK; kk += 16) {
            unsigned a[MT][4], bfr[NT][2];
#pragma unroll
            for (int mt = 0; mt < MT; mt++) {
                int r = wm * WM + mt * 16 + (grp & 1) * 8 + lr;
                int c = kk + (grp >> 1) * 8;
                ldsm4(a[mt], &As[r][c]);
            }
#pragma unroll
            for (int np = 0; np < NT; np += 2) {
                int r = wn * WN + np * 8 + (grp >> 1) * 8 + lr;
                int c = kk + (grp & 1) * 8;
                unsigned t[4];
                ldsm4(t, &Bs[r][c]);
                bfr[np][0] = t[0]; bfr[np][1] = t[1];
                bfr[np + 1][0] = t[2]; bfr[np + 1][1] = t[3];
            }
#pragma unroll
            for (int mt = 0; mt < MT; mt++)
#pragma unroll
                for (int nt = 0; nt < NT; nt++)
                    mma16816f(acc[mt][nt], a[mt], bfr[nt]);
        }
        __syncthreads();
    }

    int qr = lane >> 2, qc = (lane & 3) * 2;
#pragma unroll
    for (int mt = 0; mt < MT; mt++)
#pragma unroll
        for (int nt = 0; nt < NT; nt++) {
            int row = rb + wm * WM + mt * 16 + qr;
            int lcol = wn * WN + nt * 8 + qc;
            int col = cb + lcol;
            float2 cv = *(const float2*)&cvs[lcol];
            if (row < M)
                *(__half2*)&g_xw1h[(size_t)row * F1 + col] =
                    __floats2half2_rn(acc[mt][nt][0] + cv.x, acc[mt][nt][1] + cv.y);
            if (row + 8 < M)
                *(__half2*)&g_xw1h[(size_t)(row + 8) * F1 + col] =
                    __floats2half2_rn(acc[mt][nt][2] + cv.x, acc[mt][nt][3] + cv.y);
        }
}

// ===================== alpha1 + per-head maxes ================================
__global__ void __launch_bounds__(256) k_alpha1(const float* __restrict__ asrc,
                                                const float* __restrict__ adst, int n)
{
    __shared__ float smax[8][8];
    int wi = threadIdx.x >> 5;
    int l = threadIdx.x & 31;
    int w = blockIdx.x * 8 + wi;
    const float NEGINF = -3.402823466e38f;
    float ps1 = NEGINF, ps2 = NEGINF, pd1 = NEGINF, pd2 = NEGINF;

    if (w < n) {
        const uint2* xr = (const uint2*)(g_xw1h + (size_t)w * F1);
        float4 x1 = h4f(xr[l]), x2 = h4f(xr[32 + l]);
        float4 s1 = ((const float4*)asrc)[l], s2 = ((const float4*)asrc)[32 + l];
        float4 d1 = ((const float4*)adst)[l], d2 = ((const float4*)adst)[32 + l];
        ps1 = x1.x*s1.x + x1.y*s1.y + x1.z*s1.z + x1.w*s1.w;
        ps2 = x2.x*s2.x + x2.y*s2.y + x2.z*s2.z + x2.w*s2.w;
        pd1 = x1.x*d1.x + x1.y*d1.y + x1.z*d1.z + x1.w*d1.w;
        pd2 = x2.x*d2.x + x2.y*d2.y + x2.z*d2.z + x2.w*d2.w;
#pragma unroll
        for (int off = 8; off; off >>= 1) {
            ps1 += __shfl_xor_sync(0xffffffffu, ps1, off);
            ps2 += __shfl_xor_sync(0xffffffffu, ps2, off);
            pd1 += __shfl_xor_sync(0xffffffffu, pd1, off);
            pd2 += __shfl_xor_sync(0xffffffffu, pd2, off);
        }
        if (l == 0)  { g_as1[w*4+0] = ps1; g_as1[w*4+2] = ps2; g_ad1[w*4+0] = pd1; g_ad1[w*4+2] = pd2; }
        if (l == 16) { g_as1[w*4+1] = ps1; g_as1[w*4+3] = ps2; g_ad1[w*4+1] = pd1; g_ad1[w*4+3] = pd2; }
    }
    if (l == 0)  { smax[0][wi] = ps1; smax[2][wi] = ps2; smax[4][wi] = pd1; smax[6][wi] = pd2; }
    if (l == 16) { smax[1][wi] = ps1; smax[3][wi] = ps2; smax[5][wi] = pd1; smax[7][wi] = pd2; }
    __syncthreads();
    if (threadIdx.x < 8) {
        float m = smax[threadIdx.x][0];
#pragma unroll
        for (int k = 1; k < 8; k++) m = fmaxf(m, smax[threadIdx.x][k]);
        if (m > -3.3e38f) atomicMax(&g_emax[threadIdx.x], encf(m));
    }
}

// -------------- GAT layer-1 aggregation (warp/dst, single pass, unroll 4) ------
__global__ void __launch_bounds__(256) k_agg1(const float* __restrict__ b1, int n) {
    int w = (blockIdx.x * blockDim.x + threadIdx.x) >> 5;
    int l = threadIdx.x & 31;
    if (w >= n) return;
    int head = l >> 3;
    float adh = g_ad1[4 * w + head];
    float Mh = lrelu(dec_max(g_emax[head]) + dec_max(g_emax[4 + head]));
    int start = g_off[w], end = g_off[w + 1];

    float acc[8];
#pragma unroll
    for (int q = 0; q < 8; q++) acc[q] = 0.f;
    float den = 0.f;
    const __half* xw = g_xw1h;

    int i = start;
    for (; i + 4 <= end; i += 4) {
        int s0 = g_csrc[i], s1 = g_csrc[i + 1], s2 = g_csrc[i + 2], s3 = g_csrc[i + 3];
        float e0 = g_as1[4 * s0 + head];
        float e1 = g_as1[4 * s1 + head];
        float e2 = g_as1[4 * s2 + head];
        float e3 = g_as1[4 * s3 + head];
        uint4 x0 = *(const uint4*)(xw + (size_t)s0 * F1 + 8 * l);
        uint4 x1 = *(const uint4*)(xw + (size_t)s1 * F1 + 8 * l);
        uint4 x2 = *(const uint4*)(xw + (size_t)s2 * F1 + 8 * l);
        uint4 x3 = *(const uint4*)(xw + (size_t)s3 * F1 + 8 * l);
        float w0 = __expf(lrelu(e0 + adh) - Mh);
        float w1 = __expf(lrelu(e1 + adh) - Mh);
        float w2 = __expf(lrelu(e2 + adh) - Mh);
        float w3 = __expf(lrelu(e3 + adh) - Mh);
        den += (w0 + w1) + (w2 + w3);
        float4 a0 = h4f(make_uint2(x0.x, x0.y)), a1 = h4f(make_uint2(x0.z, x0.w));
        float4 c0 = h4f(make_uint2(x1.x, x1.y)), c1 = h4f(make_uint2(x1.z, x1.w));
        float4 d0 = h4f(make_uint2(x2.x, x2.y)), d1 = h4f(make_uint2(x2.z, x2.w));
        float4 f0 = h4f(make_uint2(x3.x, x3.y)), f1 = h4f(make_uint2(x3.z, x3.w));
        acc[0] += a0.x * w0 + c0.x * w1 + d0.x * w2 + f0.x * w3;
        acc[1] += a0.y * w0 + c0.y * w1 + d0.y * w2 + f0.y * w3;
        acc[2] += a0.z * w0 + c0.z * w1 + d0.z * w2 + f0.z * w3;
        acc[3] += a0.w * w0 + c0.w * w1 + d0.w * w2 + f0.w * w3;
        acc[4] += a1.x * w0 + c1.x * w1 + d1.x * w2 + f1.x * w3;
        acc[5] += a1.y * w0 + c1.y * w1 + d1.y * w2 + f1.y * w3;
        acc[6] += a1.z * w0 + c1.z * w1 + d1.z * w2 + f1.z * w3;
        acc[7] += a1.w * w0 + c1.w * w1 + d1.w * w2 + f1.w * w3;
    }
    for (; i < end; i++) {
        int s0 = g_csrc[i];
        float e0 = g_as1[4 * s0 + head];
        uint4 x0 = *(const uint4*)(xw + (size_t)s0 * F1 + 8 * l);
        float w0 = __expf(lrelu(e0 + adh) - Mh);
        den += w0;
        float4 a0 = h4f(make_uint2(x0.x, x0.y)), a1 = h4f(make_uint2(x0.z, x0.w));
        acc[0] += a0.x * w0; acc[1] += a0.y * w0;
        acc[2] += a0.z * w0; acc[3] += a0.w * w0;
        acc[4] += a1.x * w0; acc[5] += a1.y * w0;
        acc[6] += a1.z * w0; acc[7] += a1.w * w0;
    }
    float r = 1.f / den;
    const float* bp = b1 + 8 * l;
    float4 bb0 = *(const float4*)bp;
    float4 bb1 = *(const float4*)(bp + 4);
    __half2 q0 = __floats2half2_rn(eluf(acc[0] * r + bb0.x), eluf(acc[1] * r + bb0.y));
    __half2 q1 = __floats2half2_rn(eluf(acc[2] * r + bb0.z), eluf(acc[3] * r + bb0.w));
    __half2 q2 = __floats2half2_rn(eluf(acc[4] * r + bb1.x), eluf(acc[5] * r + bb1.y));
    __half2 q3 = __floats2half2_rn(eluf(acc[6] * r + bb1.z), eluf(acc[7] * r + bb1.w));
    uint4 st;
    st.x = *(unsigned*)&q0; st.y = *(unsigned*)&q1;
    st.z = *(unsigned*)&q2; st.w = *(unsigned*)&q3;
    *(uint4*)(g_h2h + (size_t)w * F1 + 8 * l) = st;
}

// ===================== GEMM2 (tensor cores) ===================================
__global__ void __launch_bounds__(256) k_hgemm2(int M) {
    constexpr int BM = 128, BN = 64, BK = 64, WM = 32, WN = 32, K = F1;
    constexpr int LDSM = BK + 8;
    __shared__ __align__(16) __half As[BM][LDSM];
    __shared__ __align__(16) __half Bs[BN][LDSM];

    int tid = threadIdx.x;
    int wid = tid >> 5, lane = tid & 31;
    constexpr int NWN = BN / WN;
    int wm = wid / NWN, wn = wid % NWN;
    constexpr int MT = WM / 16, NT = WN / 8;
    int rb = blockIdx.y * BM, cb = 0;
    int lr = lane & 7, grp = lane >> 3;

    float acc[MT][NT][4];
#pragma unroll
    for (int mt = 0; mt < MT; mt++)
#pragma unroll
        for (int nt = 0; nt < NT; nt++)
#pragma unroll
            for (int q = 0; q < 4; q++) acc[mt][nt][q] = 0.f;

    for (int k0 = 0; k0 < K; k0 += BK) {
        constexpr int AV = BM * BK / 8;
#pragma unroll
        for (int s = tid; s < AV; s += 256) {
            int row = s / (BK / 8), seg = s % (BK / 8);
            uint4 v = make_uint4(0u, 0u, 0u, 0u);
            if (rb + row < M) v = *(const uint4*)(g_h2h + (size_t)(rb + row) * K + k0 + seg * 8);
            *(uint4*)&As[row][seg * 8] = v;
        }
        constexpr int BV = BN * BK / 8;
#pragma unroll
        for (int s = tid; s < BV; s += 256) {
            int row = s / (BK / 8), seg = s % (BK / 8);
            *(uint4*)&Bs[row][seg * 8] = *(const uint4*)(g_w2t + (size_t)(cb + row) * K + k0 + seg * 8);
        }
        __syncthreads();
#pragma unroll
        for (int kk = 0; kk < BK; kk += 16) {
            unsigned a[MT][4], bfr[NT][2];
#pragma unroll
            for (int mt = 0; mt < MT; mt++) {
                int r = wm * WM + mt * 16 + (grp & 1) * 8 + lr;
                int c = kk + (grp >> 1) * 8;
                ldsm4(a[mt], &As[r][c]);
            }
#pragma unroll
            for (int np = 0; np < NT; np += 2) {
                int r = wn * WN + np * 8 + (grp >> 1) * 8 + lr;
                int c = kk + (grp & 1) * 8;
                unsigned t[4];
                ldsm4(t, &Bs[r][c]);
                bfr[np][0] = t[0]; bfr[np][1] = t[1];
                bfr[np + 1][0] = t[2]; bfr[np + 1][1] = t[3];
            }
#pragma unroll
            for (int mt = 0; mt < MT; mt++)
#pragma unroll
                for (int nt = 0; nt < NT; nt++)
                    mma16816f(acc[mt][nt], a[mt], bfr[nt]);
        }
        __syncthreads();
    }

    int qr = lane >> 2, qc = (lane & 3) * 2;
#pragma unroll
    for (int mt = 0; mt < MT; mt++)
#pragma unroll
        for (int nt = 0; nt < NT; nt++) {
            int row = rb + wm * WM + mt * 16 + qr;
            int col = cb + wn * WN + nt * 8 + qc;
            if (row < M)
                *(__half2*)&g_xw2h[(size_t)row * HID + col] =
                    __floats2half2_rn(acc[mt][nt][0], acc[mt][nt][1]);
            if (row + 8 < M)
                *(__half2*)&g_xw2h[(size_t)(row + 8) * HID + col] =
                    __floats2half2_rn(acc[mt][nt][2], acc[mt][nt][3]);
        }
}

// ------------------- alpha dots, layer 2 + global maxes -------------------------
__global__ void __launch_bounds__(256) k_alpha2(const float* __restrict__ asrc,
                                                const float* __restrict__ adst, int n)
{
    __shared__ float smax[2][8];
    int wi = threadIdx.x >> 5;
    int l = threadIdx.x & 31;
    int w = blockIdx.x * 8 + wi;
    const float NEGINF = -3.402823466e38f;
    float p = NEGINF, q = NEGINF;
    if (w < n) {
        __half2 hx = *(const __half2*)&g_xw2h[(size_t)w * HID + 2 * l];
        float2 xf = __half22float2(hx);
        float2 sv = ((const float2*)asrc)[l];
        float2 dv = ((const float2*)adst)[l];
        p = xf.x * sv.x + xf.y * sv.y;
        q = xf.x * dv.x + xf.y * dv.y;
#pragma unroll
        for (int off = 16; off; off >>= 1) {
            p += __shfl_xor_sync(0xffffffffu, p, off);
            q += __shfl_xor_sync(0xffffffffu, q, off);
        }
        if (l == 0) { g_as2[w] = p; g_ad2[w] = q; }
    }
    if (l == 0) { smax[0][wi] = p; smax[1][wi] = q; }
    __syncthreads();
    if (threadIdx.x < 2) {
        float m = smax[threadIdx.x][0];
#pragma unroll
        for (int k = 1; k < 8; k++) m = fmaxf(m, smax[threadIdx.x][k]);
        if (m > NEGINF) atomicMax(&g_emax[8 + threadIdx.x], encf(m));
    }
}

// -------- GAT layer-2 aggregation + fused logits + global-max ------------------
__global__ void __launch_bounds__(256) k_agg2_logits(const float* __restrict__ b2,
                                                     const float* __restrict__ Wout,
                                                     const float* __restrict__ bout,
                                                     float* __restrict__ out, int n)
{
    __shared__ float sm[8];
    int wi = threadIdx.x >> 5;
    int l = threadIdx.x & 31;
    int w = blockIdx.x * 8 + wi;
    float lg = -3.402823466e38f;

    if (w < n) {
        int start = g_off[w], end = g_off[w + 1];
        float adv = g_ad2[w];
        float M2 = lrelu(dec_max(g_emax[8]) + dec_max(g_emax[9]));

        float2 acc = make_float2(0.f, 0.f);
        float den = 0.f;
        int i = start;
        for (; i + 2 <= end; i += 2) {
            int s0 = g_csrc[i], s1 = g_csrc[i + 1];
            float e0 = __expf(lrelu(g_as2[s0] + adv) - M2);
            float e1 = __expf(lrelu(g_as2[s1] + adv) - M2);
            float2 x0 = __half22float2(*(const __half2*)&g_xw2h[(size_t)s0 * HID + 2 * l]);
            float2 x1 = __half22float2(*(const __half2*)&g_xw2h[(size_t)s1 * HID + 2 * l]);
            den += e0 + e1;
            acc.x += x0.x * e0 + x1.x * e1;
            acc.y += x0.y * e0 + x1.y * e1;
        }
        if (i < end) {
            int s0 = g_csrc[i];
            float e0 = __expf(lrelu(g_as2[s0] + adv) - M2);
            float2 x0 = __half22float2(*(const __half2*)&g_xw2h[(size_t)s0 * HID + 2 * l]);
            den += e0;
            acc.x += x0.x * e0;
            acc.y += x0.y * e0;
        }
        float r = 1.f / den;
        float2 bb = ((const float2*)b2)[l];
        float ox = eluf(acc.x * r + bb.x);
        float oy = eluf(acc.y * r + bb.y);
        // fused logits: dot with Wout
        float2 wv = ((const float2*)Wout)[l];
        float p = ox * wv.x + oy * wv.y;
#pragma unroll
        for (int off = 16; off; off >>= 1) p += __shfl_xor_sync(0xffffffffu, p, off);
        lg = p + bout[0];
        if (l == 0) out[n + w] = lg;
    }
    if (l == 0) sm[wi] = lg;
    __syncthreads();
    if (threadIdx.x == 0) {
        float mx = sm[0];
#pragma unroll
        for (int k = 1; k < 8; k++) mx = fmaxf(mx, sm[k]);
        atomicMax(&g_maxbits, encf(mx));
    }
}

__global__ void k_expsum(const float* __restrict__ out, int n) {
    __shared__ float sm[256];
    float M = dec_max(g_maxbits);
    float s = 0.f;
    for (int i = blockIdx.x * blockDim.x + threadIdx.x; i < n; i += gridDim.x * blockDim.x)
        s += __expf(out[n + i] - M);
    sm[threadIdx.x] = s;
    __syncthreads();
    for (int off = 128; off; off >>= 1) {
        if (threadIdx.x < off) sm[threadIdx.x] += sm[threadIdx.x + off];
        __syncthreads();
    }
    if (threadIdx.x == 0) atomicAdd(&g_sumexp, sm[0]);
}

__global__ void k_weights(float* __restrict__ out, int n) {
    int i = blockIdx.x * blockDim.x + threadIdx.x;
    if (i >= n) return;
    float M = dec_max(g_maxbits);
    float S = g_sumexp;
    out[i] = __expf(out[n + i] - M) / S;
}

// ------------------------- launch -------------------------
extern "C" void kernel_launch(void* const* d_in, const int* in_sizes, int n_in,
                              void* d_out, int out_size)
{
    const float* x    = (const float*)d_in[0];
    const int*   ei   = (const int*)d_in[1];
    const float* reg  = (const float*)d_in[2];
    const float* ng   = (const float*)d_in[3];
    const float* nb   = (const float*)d_in[4];
    const float* rg   = (const float*)d_in[5];
    const float* rb   = (const float*)d_in[6];
    const float* W1   = (const float*)d_in[7];
    const float* as1  = (const float*)d_in[8];
    const float* ad1  = (const float*)d_in[9];
    const float* b1   = (const float*)d_in[10];
    const float* W2   = (const float*)d_in[11];
    const float* as2  = (const float*)d_in[12];
    const float* ad2  = (const float*)d_in[13];
    const float* b2   = (const float*)d_in[14];
    const float* Wout = (const float*)d_in[15];
    const float* bout = (const float*)d_in[16];
    float* out = (float*)d_out;

    int n = in_sizes[0] / FIN;
    int e = in_sizes[1] / 2;
    int etot = e + n;
    int wb = (n + 7) / 8;
    int nbScan = (n + 1023) / 1024;
    int cntB = (etot + 1023) / 1024;

    // 1: rownorm || prepW || count || regime-LN + zeros
    k_phase1<<<wb + PWB + cntB + 1, 256>>>(x, ng, nb, reg, rg, rb, W1, W2, ei,
                                           n, e, etot, wb, cntB);
    // 2-3: scan (tiny)
    k_scanA<<<nbScan, 256>>>(n);
    k_scanC<<<nbScan, 256>>>(n, etot);

    // 4: GEMM1 || scatter
    int nGB = 2 * ((n + 127) / 128);
    k_phase2<<<nGB + cntB, 256>>>(W1, ei, n, e, etot, nGB);

    // 5: alpha1
    k_alpha1<<<wb, 256>>>(as1, ad1, n);

    // 6: agg1 (profiled slot)
    k_agg1<<<wb, 256>>>(b1, n);

    // 7: GEMM2
    dim3 g2(1, (n + 127) / 128);
    k_hgemm2<<<g2, 256>>>(n);

    // 8: alpha2
    k_alpha2<<<wb, 256>>>(as2, ad2, n);

    // 9: agg2 + logits
    k_agg2_logits<<<wb, 256>>>(b2, Wout, bout, out, n);

    // 10-11: global softmax
    k_expsum<<<256, 256>>>(out, n);
    k_weights<<<(n + 255) / 256, 256>>>(out, n);
}